// round 4
// baseline (speedup 1.0000x reference)
#include <cuda_runtime.h>

#define D_  512
#define B_  8
#define S_  2048
#define F_  2048
#define L_  4
#define BS_ (B_*S_)

// ---------------- scratch (static device globals; no allocation) ----------------
__device__ float g_x [BS_*D_];                 // activations            [16384,512]
__device__ float g_q [BS_*D_];
__device__ float g_k [BS_*D_];
__device__ float g_v [BS_*D_];
__device__ float g_t [BS_*D_];
__device__ float g_h [(size_t)BS_*F_];         // FFN hidden             [16384,2048]
__device__ float g_sc[(size_t)B_*S_*S_];       // attention scores       [8,2048,2048]

// ---------------- embedding + sinusoidal PE ----------------
__global__ void embed_kernel(const int* __restrict__ tok,
                             const float* __restrict__ emb,
                             float* __restrict__ x)
{
    int idx = blockIdx.x * blockDim.x + threadIdx.x;      // over BS_*D_
    int d  = idx & (D_ - 1);
    int bs = idx >> 9;                                    // D_=512
    int s  = bs & (S_ - 1);
    int t  = tok[bs];
    // div = exp(-(2i) * ln(10000)/D), d = 2i or 2i+1
    float dv  = expf(-(float)(d & ~1) * (9.210340371976184f / (float)D_));
    float arg = (float)s * dv;
    float pe  = (d & 1) ? cosf(arg) : sinf(arg);
    x[idx] = emb[(size_t)t * D_ + d] + pe;
}

// ---------------- fp32 GEMM: C = scale*(A @ op(B)) [+bias] [relu] ----------------
// A: [M,K] row-major.  NT=0: B [K,N] row-major.  NT=1: B [N,K] row-major (B^T).
// 128x128 tile, BK=8, 256 threads, 8x8 per thread.
#define TS 128
#define KS 8

template<int NT>
__global__ __launch_bounds__(256)
void gemm_kernel(const float* __restrict__ A, const float* __restrict__ B,
                 const float* __restrict__ bias, float* __restrict__ C,
                 int M, int N, int K,
                 long long sA, long long sB, long long sC,
                 float scale, int relu)
{
    __shared__ float As[KS][TS];
    __shared__ float Bs[KS][TS];

    const int tid = threadIdx.x;
    A += (long long)blockIdx.z * sA + (long long)blockIdx.y * TS * K;
    C += (long long)blockIdx.z * sC + (long long)blockIdx.y * TS * N + (long long)blockIdx.x * TS;
    if (NT) B += (long long)blockIdx.z * sB + (long long)blockIdx.x * TS * K;
    else    B += (long long)blockIdx.z * sB + blockIdx.x * TS;

    const int arow = tid >> 1;               // 0..127
    const int akc  = (tid & 1) * 4;          // 0 or 4
    const int brow = tid >> 5;               // 0..7   (NN)
    const int bcol = (tid & 31) * 4;         // 0..124 (NN)
    const int tx   = tid & 15;
    const int ty   = tid >> 4;

    float acc[8][8];
#pragma unroll
    for (int i = 0; i < 8; i++)
#pragma unroll
        for (int j = 0; j < 8; j++) acc[i][j] = 0.f;

    for (int k0 = 0; k0 < K; k0 += KS) {
        float4 a4 = *(const float4*)(A + (long long)arow * K + k0 + akc);
        As[akc + 0][arow] = a4.x;
        As[akc + 1][arow] = a4.y;
        As[akc + 2][arow] = a4.z;
        As[akc + 3][arow] = a4.w;
        if (NT) {
            float4 b4 = *(const float4*)(B + (long long)arow * K + k0 + akc);
            Bs[akc + 0][arow] = b4.x;
            Bs[akc + 1][arow] = b4.y;
            Bs[akc + 2][arow] = b4.z;
            Bs[akc + 3][arow] = b4.w;
        } else {
            float4 b4 = *(const float4*)(B + (long long)(k0 + brow) * N + bcol);
            *(float4*)&Bs[brow][bcol] = b4;
        }
        __syncthreads();

#pragma unroll
        for (int kk = 0; kk < KS; kk++) {
            float4 a0 = *(const float4*)&As[kk][ty * 8];
            float4 a1 = *(const float4*)&As[kk][ty * 8 + 4];
            float4 b0 = *(const float4*)&Bs[kk][tx * 8];
            float4 b1 = *(const float4*)&Bs[kk][tx * 8 + 4];
            float av[8] = {a0.x, a0.y, a0.z, a0.w, a1.x, a1.y, a1.z, a1.w};
            float bv[8] = {b0.x, b0.y, b0.z, b0.w, b1.x, b1.y, b1.z, b1.w};
#pragma unroll
            for (int i = 0; i < 8; i++)
#pragma unroll
                for (int j = 0; j < 8; j++)
                    acc[i][j] = fmaf(av[i], bv[j], acc[i][j]);
        }
        __syncthreads();
    }

#pragma unroll
    for (int i = 0; i < 8; i++) {
        long long row = ty * 8 + i;
        float4 v0, v1;
        float* o = (float*)&v0;
#pragma unroll
        for (int j = 0; j < 8; j++) {
            float val = acc[i][j] * scale;
            if (bias) val += bias[blockIdx.x * TS + tx * 8 + j];
            if (relu) val = fmaxf(val, 0.f);
            ((float*)&v0)[0] = ((float*)&v0)[0]; // keep compiler calm
            if (j < 4) ((float*)&v0)[j] = val; else ((float*)&v1)[j - 4] = val;
        }
        (void)o;
        *(float4*)(C + row * N + tx * 8)     = v0;
        *(float4*)(C + row * N + tx * 8 + 4) = v1;
    }
}

// ---------------- row softmax (in place), row length S_, with pre-scale ----------------
__global__ __launch_bounds__(256)
void softmax_kernel(float* __restrict__ sc, float scale)
{
    __shared__ float red[256];
    const long long row = blockIdx.x;
    float* p = sc + row * (long long)S_;
    const int tid = threadIdx.x;

    float v[8];
    float m = -1e30f;
#pragma unroll
    for (int i = 0; i < 8; i++) {
        v[i] = p[tid + i * 256] * scale;
        m = fmaxf(m, v[i]);
    }
    red[tid] = m; __syncthreads();
    for (int o = 128; o > 0; o >>= 1) {
        if (tid < o) red[tid] = fmaxf(red[tid], red[tid + o]);
        __syncthreads();
    }
    m = red[0]; __syncthreads();

    float s = 0.f;
#pragma unroll
    for (int i = 0; i < 8; i++) { v[i] = expf(v[i] - m); s += v[i]; }
    red[tid] = s; __syncthreads();
    for (int o = 128; o > 0; o >>= 1) {
        if (tid < o) red[tid] += red[tid + o];
        __syncthreads();
    }
    float inv = 1.f / red[0];
#pragma unroll
    for (int i = 0; i < 8; i++) p[tid + i * 256] = v[i] * inv;
}

// ---------------- residual + layernorm (in place on x) ----------------
__global__ __launch_bounds__(128)
void ln_kernel(float* __restrict__ x, const float* __restrict__ r,
               const float* __restrict__ g, const float* __restrict__ b)
{
    __shared__ float red[128];
    const long long row = blockIdx.x;
    const int tid = threadIdx.x;
    float* px = x + row * (long long)D_;
    const float* pr = r + row * (long long)D_;

    float v[4];
    float s = 0.f;
#pragma unroll
    for (int i = 0; i < 4; i++) {
        v[i] = px[tid + i * 128] + pr[tid + i * 128];
        s += v[i];
    }
    red[tid] = s; __syncthreads();
    for (int o = 64; o > 0; o >>= 1) {
        if (tid < o) red[tid] += red[tid + o];
        __syncthreads();
    }
    const float mu = red[0] * (1.f / D_); __syncthreads();

    float sq = 0.f;
#pragma unroll
    for (int i = 0; i < 4; i++) { float d = v[i] - mu; sq += d * d; }
    red[tid] = sq; __syncthreads();
    for (int o = 64; o > 0; o >>= 1) {
        if (tid < o) red[tid] += red[tid + o];
        __syncthreads();
    }
    const float rstd = rsqrtf(red[0] * (1.f / D_) + 1e-5f);
#pragma unroll
    for (int i = 0; i < 4; i++) {
        int c = tid + i * 128;
        px[c] = (v[i] - mu) * rstd * g[c] + b[c];
    }
}

// ---------------- mean-pool over S then dot with clf_w ----------------
__global__ __launch_bounds__(256)
void pool_kernel(const float* __restrict__ x, const float* __restrict__ w,
                 const float* __restrict__ cb, float* __restrict__ out)
{
    __shared__ float red[256];
    const int b = blockIdx.x;
    const int tid = threadIdx.x;
    const float* p = x + (long long)b * S_ * D_;
    float acc = 0.f;
    for (int i = tid; i < S_ * D_; i += 256)
        acc += p[i] * w[i & (D_ - 1)];
    red[tid] = acc; __syncthreads();
    for (int o = 128; o > 0; o >>= 1) {
        if (tid < o) red[tid] += red[tid + o];
        __syncthreads();
    }
    if (tid == 0) out[b] = red[0] * (1.f / (float)S_) + cb[0];
}

// ---------------- host orchestration ----------------
extern "C" void kernel_launch(void* const* d_in, const int* in_sizes, int n_in,
                              void* d_out, int out_size)
{
    (void)in_sizes; (void)n_in; (void)out_size;
    const int*   tokens = (const int*)  d_in[0];
    const float* emb    = (const float*)d_in[1];
    const float* Wq     = (const float*)d_in[2];
    const float* bq     = (const float*)d_in[3];
    const float* Wk     = (const float*)d_in[4];
    const float* bk     = (const float*)d_in[5];
    const float* Wv     = (const float*)d_in[6];
    const float* bv     = (const float*)d_in[7];
    const float* Wo     = (const float*)d_in[8];
    const float* bo     = (const float*)d_in[9];
    const float* W1     = (const float*)d_in[10];
    const float* b1     = (const float*)d_in[11];
    const float* W2     = (const float*)d_in[12];
    const float* b2     = (const float*)d_in[13];
    const float* ln1g   = (const float*)d_in[14];
    const float* ln1b   = (const float*)d_in[15];
    const float* ln2g   = (const float*)d_in[16];
    const float* ln2b   = (const float*)d_in[17];
    const float* clfw   = (const float*)d_in[18];
    const float* clfb   = (const float*)d_in[19];
    float* out = (float*)d_out;

    float *x, *q, *k, *v, *t, *h, *sc;
    cudaGetSymbolAddress((void**)&x,  g_x);
    cudaGetSymbolAddress((void**)&q,  g_q);
    cudaGetSymbolAddress((void**)&k,  g_k);
    cudaGetSymbolAddress((void**)&v,  g_v);
    cudaGetSymbolAddress((void**)&t,  g_t);
    cudaGetSymbolAddress((void**)&h,  g_h);
    cudaGetSymbolAddress((void**)&sc, g_sc);

    embed_kernel<<<(BS_ * D_) / 256, 256>>>(tokens, emb, x);

    const dim3 gProj(D_ / TS, BS_ / TS, 1);       // [16384,512] = x @ [512,512]
    const dim3 gScores(S_ / TS, S_ / TS, B_);     // per-batch [2048,2048]
    const dim3 gAV(D_ / TS, S_ / TS, B_);         // per-batch [2048,512]
    const dim3 gF1(F_ / TS, BS_ / TS, 1);         // [16384,2048]
    const float kscale = 0.044194173824159216f;   // 1/sqrt(512)

    for (int l = 0; l < L_; l++) {
        const float* Wq_l = Wq + (size_t)l * D_ * D_;
        const float* Wk_l = Wk + (size_t)l * D_ * D_;
        const float* Wv_l = Wv + (size_t)l * D_ * D_;
        const float* Wo_l = Wo + (size_t)l * D_ * D_;
        const float* W1_l = W1 + (size_t)l * D_ * F_;
        const float* W2_l = W2 + (size_t)l * F_ * D_;
        const float* bq_l = bq + (size_t)l * D_;
        const float* bk_l = bk + (size_t)l * D_;
        const float* bv_l = bv + (size_t)l * D_;
        const float* bo_l = bo + (size_t)l * D_;
        const float* b1_l = b1 + (size_t)l * F_;
        const float* b2_l = b2 + (size_t)l * D_;

        gemm_kernel<0><<<gProj, 256>>>(x, Wq_l, bq_l, q, BS_, D_, D_, 0, 0, 0, 1.f, 0);
        gemm_kernel<0><<<gProj, 256>>>(x, Wk_l, bk_l, k, BS_, D_, D_, 0, 0, 0, 1.f, 0);
        gemm_kernel<0><<<gProj, 256>>>(x, Wv_l, bv_l, v, BS_, D_, D_, 0, 0, 0, 1.f, 0);

        // scores[b] = q_b @ k_b^T   (scale applied in softmax)
        gemm_kernel<1><<<gScores, 256>>>(q, k, nullptr, sc, S_, S_, D_,
                                         (long long)S_ * D_, (long long)S_ * D_,
                                         (long long)S_ * S_, 1.f, 0);
        softmax_kernel<<<B_ * S_, 256>>>(sc, kscale);

        // t[b] = attn_b @ v_b
        gemm_kernel<0><<<gAV, 256>>>(sc, v, nullptr, t, S_, D_, S_,
                                     (long long)S_ * S_, (long long)S_ * D_,
                                     (long long)S_ * D_, 1.f, 0);

        // attn_out = t @ Wo + bo  (reuse q)
        gemm_kernel<0><<<gProj, 256>>>(t, Wo_l, bo_l, q, BS_, D_, D_, 0, 0, 0, 1.f, 0);
        ln_kernel<<<BS_, 128>>>(x, q, ln1g + (size_t)l * D_, ln1b + (size_t)l * D_);

        // FFN
        gemm_kernel<0><<<gF1, 256>>>(x, W1_l, b1_l, h, BS_, F_, D_, 0, 0, 0, 1.f, 1);
        gemm_kernel<0><<<gProj, 256>>>(h, W2_l, b2_l, t, BS_, D_, F_, 0, 0, 0, 1.f, 0);
        ln_kernel<<<BS_, 128>>>(x, t, ln2g + (size_t)l * D_, ln2b + (size_t)l * D_);
    }

    pool_kernel<<<B_, 256>>>(x, clfw, clfb, out);
}

// round 5
// speedup vs baseline: 3.2210x; 3.2210x over previous
#include <cuda_runtime.h>
#include <cstdint>

#define D_  512
#define B_  8
#define S_  2048
#define F_  2048
#define L_  4
#define BS_ (B_*S_)

// ---------------- scratch (static device globals; no allocation) ----------------
__device__ float g_x [BS_*D_];
__device__ float g_q [BS_*D_];
__device__ float g_k [BS_*D_];
__device__ float g_v [BS_*D_];
__device__ float g_t [BS_*D_];
__device__ float g_h [(size_t)BS_*F_];
__device__ float g_sc[(size_t)B_*S_*S_];

// ---------------- embedding + sinusoidal PE ----------------
__global__ void embed_kernel(const int* __restrict__ tok,
                             const float* __restrict__ emb,
                             float* __restrict__ x)
{
    int idx = blockIdx.x * blockDim.x + threadIdx.x;
    int d  = idx & (D_ - 1);
    int bs = idx >> 9;
    int s  = bs & (S_ - 1);
    int t  = tok[bs];
    float dv  = expf(-(float)(d & ~1) * (9.210340371976184f / (float)D_));
    float arg = (float)s * dv;
    float pe  = (d & 1) ? cosf(arg) : sinf(arg);
    x[idx] = emb[(size_t)t * D_ + d] + pe;
}

// ---------------- tf32 tensor-core GEMM ----------------
// C = scale*(A @ op(B)) [+bias] [relu]
// A: [M,K] row-major. NT=0: B [K,N] row-major. NT=1: B [N,K] row-major (B^T).
// 128x128x16 tile, 256 threads (8 warps, 2x4), warp tile 64x32, double-buffered cp.async.

#define BM 128
#define BN 128
#define BK 16
#define ASTRIDE 20            // padded: banks (20r+c)%32 all-distinct for r0..7,c0..3
#define ASIZE   (128*ASTRIDE) // floats
#define BSTRIDE_NN 136        // banks (8k+n)%32 all-distinct
#define BSIZE_NN  (16*BSTRIDE_NN)
#define BSIZE_NT  (128*ASTRIDE)

__device__ __forceinline__ uint32_t f2tf(float f) {
    uint32_t u; asm("cvt.rna.tf32.f32 %0, %1;" : "=r"(u) : "f"(f)); return u;
}
__device__ __forceinline__ void mma8(float* c, const uint32_t* a, const uint32_t* b) {
    asm volatile(
        "mma.sync.aligned.m16n8k8.row.col.f32.tf32.tf32.f32 "
        "{%0,%1,%2,%3},{%4,%5,%6,%7},{%8,%9},{%0,%1,%2,%3};"
        : "+f"(c[0]), "+f"(c[1]), "+f"(c[2]), "+f"(c[3])
        : "r"(a[0]), "r"(a[1]), "r"(a[2]), "r"(a[3]), "r"(b[0]), "r"(b[1]));
}
__device__ __forceinline__ void cp16(uint32_t dst, const void* src) {
    asm volatile("cp.async.cg.shared.global [%0], [%1], 16;" :: "r"(dst), "l"(src));
}

template<int NT>
__global__ __launch_bounds__(256)
void gemm_tc(const float* __restrict__ A, const float* __restrict__ B,
             const float* __restrict__ bias, float* __restrict__ C,
             int M, int N, int K,
             long long sA, long long sB, long long sC,
             float scale, int relu)
{
    constexpr int BSIZE = NT ? BSIZE_NT : BSIZE_NN;
    __shared__ float As[2 * ASIZE];
    __shared__ float Bs[2 * BSIZE];

    const int tid  = threadIdx.x;
    const int lane = tid & 31;
    const int wid  = tid >> 5;
    const int wm   = wid >> 2;          // 0..1  (M dir)
    const int wn   = wid & 3;           // 0..3  (N dir)
    const int lr   = lane >> 2;         // 0..7
    const int lc   = lane & 3;          // 0..3

    A += (long long)blockIdx.z * sA + (long long)blockIdx.y * BM * K;
    C += (long long)blockIdx.z * sC + (long long)blockIdx.y * BM * N + (long long)blockIdx.x * BN;
    if (NT) B += (long long)blockIdx.z * sB + (long long)blockIdx.x * BN * K;
    else    B += (long long)blockIdx.z * sB + blockIdx.x * BN;

    const uint32_t sA0 = (uint32_t)__cvta_generic_to_shared(As);
    const uint32_t sB0 = (uint32_t)__cvta_generic_to_shared(Bs);

    float acc[4][4][4];
#pragma unroll
    for (int i = 0; i < 4; i++)
#pragma unroll
        for (int j = 0; j < 4; j++)
#pragma unroll
            for (int r = 0; r < 4; r++) acc[i][j][r] = 0.f;

    const int ntiles = K / BK;

    auto load_tile = [&](int buf, int k0) {
#pragma unroll
        for (int i = 0; i < 2; i++) {
            int idx = tid + i * 256;                 // 0..511
            int row = idx >> 2, kc = (idx & 3) * 4;
            cp16(sA0 + (buf * ASIZE + row * ASTRIDE + kc) * 4,
                 A + (long long)row * K + k0 + kc);
        }
        if (NT) {
#pragma unroll
            for (int i = 0; i < 2; i++) {
                int idx = tid + i * 256;
                int n = idx >> 2, kc = (idx & 3) * 4;
                cp16(sB0 + (buf * BSIZE + n * ASTRIDE + kc) * 4,
                     B + (long long)n * K + k0 + kc);
            }
        } else {
#pragma unroll
            for (int i = 0; i < 2; i++) {
                int idx = tid + i * 256;
                int kr = idx >> 5, nc = (idx & 31) * 4;
                cp16(sB0 + (buf * BSIZE + kr * BSTRIDE_NN + nc) * 4,
                     B + (long long)(k0 + kr) * N + nc);
            }
        }
        asm volatile("cp.async.commit_group;");
    };

    load_tile(0, 0);
    int buf = 0;
    for (int t = 0; t < ntiles; t++) {
        if (t + 1 < ntiles) {
            load_tile(buf ^ 1, (t + 1) * BK);
            asm volatile("cp.async.wait_group 1;");
        } else {
            asm volatile("cp.async.wait_group 0;");
        }
        __syncthreads();

        const float* as = As + buf * ASIZE;
        const float* bs = Bs + buf * BSIZE;
#pragma unroll
        for (int ks = 0; ks < BK; ks += 8) {
            uint32_t a[4][4], b[4][2];
#pragma unroll
            for (int i = 0; i < 4; i++) {
                int r = wm * 64 + i * 16 + lr;
                int c = ks + lc;
                a[i][0] = f2tf(as[r * ASTRIDE + c]);
                a[i][1] = f2tf(as[(r + 8) * ASTRIDE + c]);
                a[i][2] = f2tf(as[r * ASTRIDE + c + 4]);
                a[i][3] = f2tf(as[(r + 8) * ASTRIDE + c + 4]);
            }
#pragma unroll
            for (int j = 0; j < 4; j++) {
                int n = wn * 32 + j * 8 + lr;
                int k = ks + lc;
                if (NT) {
                    b[j][0] = f2tf(bs[n * ASTRIDE + k]);
                    b[j][1] = f2tf(bs[n * ASTRIDE + k + 4]);
                } else {
                    b[j][0] = f2tf(bs[k * BSTRIDE_NN + n]);
                    b[j][1] = f2tf(bs[(k + 4) * BSTRIDE_NN + n]);
                }
            }
#pragma unroll
            for (int i = 0; i < 4; i++)
#pragma unroll
                for (int j = 0; j < 4; j++)
                    mma8(acc[i][j], a[i], b[j]);
        }
        __syncthreads();
        buf ^= 1;
    }

    // epilogue
#pragma unroll
    for (int i = 0; i < 4; i++) {
        int r0 = wm * 64 + i * 16 + lr;
#pragma unroll
        for (int j = 0; j < 4; j++) {
            int col = wn * 32 + j * 8 + 2 * lc;
            float b0 = 0.f, b1 = 0.f;
            if (bias) {
                b0 = bias[blockIdx.x * BN + col];
                b1 = bias[blockIdx.x * BN + col + 1];
            }
            float v0 = acc[i][j][0] * scale + b0;
            float v1 = acc[i][j][1] * scale + b1;
            float v2 = acc[i][j][2] * scale + b0;
            float v3 = acc[i][j][3] * scale + b1;
            if (relu) {
                v0 = fmaxf(v0, 0.f); v1 = fmaxf(v1, 0.f);
                v2 = fmaxf(v2, 0.f); v3 = fmaxf(v3, 0.f);
            }
            *(float2*)(C + (long long)r0 * N + col)       = make_float2(v0, v1);
            *(float2*)(C + (long long)(r0 + 8) * N + col) = make_float2(v2, v3);
        }
    }
}

// ---------------- row softmax (in place), row length S_, with pre-scale ----------------
__global__ __launch_bounds__(256)
void softmax_kernel(float* __restrict__ sc, float scale)
{
    __shared__ float red[256];
    const long long row = blockIdx.x;
    float* p = sc + row * (long long)S_;
    const int tid = threadIdx.x;

    float v[8];
    float m = -1e30f;
#pragma unroll
    for (int i = 0; i < 8; i++) {
        v[i] = p[tid + i * 256] * scale;
        m = fmaxf(m, v[i]);
    }
    red[tid] = m; __syncthreads();
    for (int o = 128; o > 0; o >>= 1) {
        if (tid < o) red[tid] = fmaxf(red[tid], red[tid + o]);
        __syncthreads();
    }
    m = red[0]; __syncthreads();

    float s = 0.f;
#pragma unroll
    for (int i = 0; i < 8; i++) { v[i] = expf(v[i] - m); s += v[i]; }
    red[tid] = s; __syncthreads();
    for (int o = 128; o > 0; o >>= 1) {
        if (tid < o) red[tid] += red[tid + o];
        __syncthreads();
    }
    float inv = 1.f / red[0];
#pragma unroll
    for (int i = 0; i < 8; i++) p[tid + i * 256] = v[i] * inv;
}

// ---------------- residual + layernorm (in place on x) ----------------
__global__ __launch_bounds__(128)
void ln_kernel(float* __restrict__ x, const float* __restrict__ r,
               const float* __restrict__ g, const float* __restrict__ b)
{
    __shared__ float red[128];
    const long long row = blockIdx.x;
    const int tid = threadIdx.x;
    float* px = x + row * (long long)D_;
    const float* pr = r + row * (long long)D_;

    float v[4];
    float s = 0.f;
#pragma unroll
    for (int i = 0; i < 4; i++) {
        v[i] = px[tid + i * 128] + pr[tid + i * 128];
        s += v[i];
    }
    red[tid] = s; __syncthreads();
    for (int o = 64; o > 0; o >>= 1) {
        if (tid < o) red[tid] += red[tid + o];
        __syncthreads();
    }
    const float mu = red[0] * (1.f / D_); __syncthreads();

    float sq = 0.f;
#pragma unroll
    for (int i = 0; i < 4; i++) { float d = v[i] - mu; sq += d * d; }
    red[tid] = sq; __syncthreads();
    for (int o = 64; o > 0; o >>= 1) {
        if (tid < o) red[tid] += red[tid + o];
        __syncthreads();
    }
    const float rstd = rsqrtf(red[0] * (1.f / D_) + 1e-5f);
#pragma unroll
    for (int i = 0; i < 4; i++) {
        int c = tid + i * 128;
        px[c] = (v[i] - mu) * rstd * g[c] + b[c];
    }
}

// ---------------- mean-pool over S then dot with clf_w ----------------
__global__ __launch_bounds__(256)
void pool_kernel(const float* __restrict__ x, const float* __restrict__ w,
                 const float* __restrict__ cb, float* __restrict__ out)
{
    __shared__ float red[256];
    const int b = blockIdx.x;
    const int tid = threadIdx.x;
    const float* p = x + (long long)b * S_ * D_;
    float acc = 0.f;
    for (int i = tid; i < S_ * D_; i += 256)
        acc += p[i] * w[i & (D_ - 1)];
    red[tid] = acc; __syncthreads();
    for (int o = 128; o > 0; o >>= 1) {
        if (tid < o) red[tid] += red[tid + o];
        __syncthreads();
    }
    if (tid == 0) out[b] = red[0] * (1.f / (float)S_) + cb[0];
}

// ---------------- host orchestration ----------------
extern "C" void kernel_launch(void* const* d_in, const int* in_sizes, int n_in,
                              void* d_out, int out_size)
{
    (void)in_sizes; (void)n_in; (void)out_size;
    const int*   tokens = (const int*)  d_in[0];
    const float* emb    = (const float*)d_in[1];
    const float* Wq     = (const float*)d_in[2];
    const float* bq     = (const float*)d_in[3];
    const float* Wk     = (const float*)d_in[4];
    const float* bk     = (const float*)d_in[5];
    const float* Wv     = (const float*)d_in[6];
    const float* bv     = (const float*)d_in[7];
    const float* Wo     = (const float*)d_in[8];
    const float* bo     = (const float*)d_in[9];
    const float* W1     = (const float*)d_in[10];
    const float* b1     = (const float*)d_in[11];
    const float* W2     = (const float*)d_in[12];
    const float* b2     = (const float*)d_in[13];
    const float* ln1g   = (const float*)d_in[14];
    const float* ln1b   = (const float*)d_in[15];
    const float* ln2g   = (const float*)d_in[16];
    const float* ln2b   = (const float*)d_in[17];
    const float* clfw   = (const float*)d_in[18];
    const float* clfb   = (const float*)d_in[19];
    float* out = (float*)d_out;

    float *x, *q, *k, *v, *t, *h, *sc;
    cudaGetSymbolAddress((void**)&x,  g_x);
    cudaGetSymbolAddress((void**)&q,  g_q);
    cudaGetSymbolAddress((void**)&k,  g_k);
    cudaGetSymbolAddress((void**)&v,  g_v);
    cudaGetSymbolAddress((void**)&t,  g_t);
    cudaGetSymbolAddress((void**)&h,  g_h);
    cudaGetSymbolAddress((void**)&sc, g_sc);

    embed_kernel<<<(BS_ * D_) / 256, 256>>>(tokens, emb, x);

    const dim3 gProj(D_ / BN, BS_ / BM, 1);
    const dim3 gScores(S_ / BN, S_ / BM, B_);
    const dim3 gAV(D_ / BN, S_ / BM, B_);
    const dim3 gF1(F_ / BN, BS_ / BM, 1);
    const float kscale = 0.044194173824159216f;   // 1/sqrt(512)

    for (int l = 0; l < L_; l++) {
        const float* Wq_l = Wq + (size_t)l * D_ * D_;
        const float* Wk_l = Wk + (size_t)l * D_ * D_;
        const float* Wv_l = Wv + (size_t)l * D_ * D_;
        const float* Wo_l = Wo + (size_t)l * D_ * D_;
        const float* W1_l = W1 + (size_t)l * D_ * F_;
        const float* W2_l = W2 + (size_t)l * F_ * D_;
        const float* bq_l = bq + (size_t)l * D_;
        const float* bk_l = bk + (size_t)l * D_;
        const float* bv_l = bv + (size_t)l * D_;
        const float* bo_l = bo + (size_t)l * D_;
        const float* b1_l = b1 + (size_t)l * F_;
        const float* b2_l = b2 + (size_t)l * D_;

        gemm_tc<0><<<gProj, 256>>>(x, Wq_l, bq_l, q, BS_, D_, D_, 0, 0, 0, 1.f, 0);
        gemm_tc<0><<<gProj, 256>>>(x, Wk_l, bk_l, k, BS_, D_, D_, 0, 0, 0, 1.f, 0);
        gemm_tc<0><<<gProj, 256>>>(x, Wv_l, bv_l, v, BS_, D_, D_, 0, 0, 0, 1.f, 0);

        // scores[b] = q_b @ k_b^T  (scale applied in softmax)
        gemm_tc<1><<<gScores, 256>>>(q, k, nullptr, sc, S_, S_, D_,
                                     (long long)S_ * D_, (long long)S_ * D_,
                                     (long long)S_ * S_, 1.f, 0);
        softmax_kernel<<<B_ * S_, 256>>>(sc, kscale);

        // t[b] = attn_b @ v_b
        gemm_tc<0><<<gAV, 256>>>(sc, v, nullptr, t, S_, D_, S_,
                                 (long long)S_ * S_, (long long)S_ * D_,
                                 (long long)S_ * D_, 1.f, 0);

        // attn_out = t @ Wo + bo  (reuse q)
        gemm_tc<0><<<gProj, 256>>>(t, Wo_l, bo_l, q, BS_, D_, D_, 0, 0, 0, 1.f, 0);
        ln_kernel<<<BS_, 128>>>(x, q, ln1g + (size_t)l * D_, ln1b + (size_t)l * D_);

        // FFN
        gemm_tc<0><<<gF1, 256>>>(x, W1_l, b1_l, h, BS_, F_, D_, 0, 0, 0, 1.f, 1);
        gemm_tc<0><<<gProj, 256>>>(h, W2_l, b2_l, t, BS_, D_, F_, 0, 0, 0, 1.f, 0);
        ln_kernel<<<BS_, 128>>>(x, t, ln2g + (size_t)l * D_, ln2b + (size_t)l * D_);
    }

    pool_kernel<<<B_, 256>>>(x, clfw, clfb, out);
}

// round 6
// speedup vs baseline: 4.2817x; 1.3293x over previous
#include <cuda_runtime.h>
#include <cuda_bf16.h>
#include <cstdint>

typedef __nv_bfloat16 bf16;

#define D_  512
#define B_  8
#define S_  2048
#define F_  2048
#define L_  4
#define BS_ (B_*S_)

// ---------------- scratch (static device globals; no allocation) ----------------
__device__ float g_x [BS_*D_];                  // f32 master activations
__device__ float g_r [BS_*D_];                  // f32 residual branch
__device__ float g_sc[(size_t)B_*S_*S_];        // f32 attention scores
__device__ bf16  g_xb[BS_*D_];                  // bf16 copies for GEMM A/B operands
__device__ bf16  g_qb[BS_*D_];
__device__ bf16  g_kb[BS_*D_];
__device__ bf16  g_vb[BS_*D_];
__device__ bf16  g_tb[BS_*D_];
__device__ bf16  g_hb[(size_t)BS_*F_];
__device__ bf16  g_pb[(size_t)B_*S_*S_];        // bf16 softmax probs
__device__ bf16  g_wqb[L_*D_*D_];
__device__ bf16  g_wkb[L_*D_*D_];
__device__ bf16  g_wvb[L_*D_*D_];
__device__ bf16  g_wob[L_*D_*D_];
__device__ bf16  g_w1b[(size_t)L_*D_*F_];
__device__ bf16  g_w2b[(size_t)L_*D_*F_];

// ---------------- f32 -> bf16 convert (weights) ----------------
__global__ void cvt_bf(const float* __restrict__ s, bf16* __restrict__ d)
{
    int i = blockIdx.x * 256 + threadIdx.x;
    d[i] = __float2bfloat16(s[i]);
}

// ---------------- embedding + sinusoidal PE (f32 + bf16 out) ----------------
__global__ void embed_kernel(const int* __restrict__ tok,
                             const float* __restrict__ emb,
                             float* __restrict__ x, bf16* __restrict__ xb)
{
    int idx = blockIdx.x * blockDim.x + threadIdx.x;
    int d  = idx & (D_ - 1);
    int bs = idx >> 9;
    int s  = bs & (S_ - 1);
    int t  = tok[bs];
    float dv  = expf(-(float)(d & ~1) * (9.210340371976184f / (float)D_));
    float arg = (float)s * dv;
    float pe  = (d & 1) ? cosf(arg) : sinf(arg);
    float v = emb[(size_t)t * D_ + d] + pe;
    x[idx]  = v;
    xb[idx] = __float2bfloat16(v);
}

// ---------------- bf16 tensor-core GEMM ----------------
// C = scale*(A @ op(B)) [+bias] [relu]
// A: [M,K] bf16 row-major. NT=0: B [K,N] bf16 row-major. NT=1: B [N,K] bf16 (B^T).
// OUTB=1: C bf16; OUTB=0: C f32.
// 128x128x32 tile, 256 threads (8 warps 2x4, warp 64x32), double-buffered cp.async,
// XOR-swizzled smem, ldmatrix fragment loads, m16n8k16 MMA.

#define BM 128
#define BN 128
#define BK 32

__device__ __forceinline__ void cp16(uint32_t dst, const void* src) {
    asm volatile("cp.async.cg.shared.global [%0], [%1], 16;" :: "r"(dst), "l"(src));
}
__device__ __forceinline__ void ldsm4(uint32_t* r, uint32_t addr) {
    asm volatile("ldmatrix.sync.aligned.m8n8.x4.shared.b16 {%0,%1,%2,%3}, [%4];"
        : "=r"(r[0]), "=r"(r[1]), "=r"(r[2]), "=r"(r[3]) : "r"(addr));
}
__device__ __forceinline__ void ldsm4t(uint32_t* r, uint32_t addr) {
    asm volatile("ldmatrix.sync.aligned.m8n8.x4.trans.shared.b16 {%0,%1,%2,%3}, [%4];"
        : "=r"(r[0]), "=r"(r[1]), "=r"(r[2]), "=r"(r[3]) : "r"(addr));
}
__device__ __forceinline__ void mma16(float* c, const uint32_t* a, const uint32_t* b) {
    asm volatile(
        "mma.sync.aligned.m16n8k16.row.col.f32.bf16.bf16.f32 "
        "{%0,%1,%2,%3},{%4,%5,%6,%7},{%8,%9},{%0,%1,%2,%3};"
        : "+f"(c[0]), "+f"(c[1]), "+f"(c[2]), "+f"(c[3])
        : "r"(a[0]), "r"(a[1]), "r"(a[2]), "r"(a[3]), "r"(b[0]), "r"(b[1]));
}

template<int NT, int OUTB>
__global__ __launch_bounds__(256, 2)
void gemm_bf(const bf16* __restrict__ A, const bf16* __restrict__ B,
             const float* __restrict__ bias, void* __restrict__ Cv,
             int M, int N, int K,
             long long sA, long long sB, long long sC,
             float scale, int relu)
{
    // As: 128 rows x 128B (two BK=32 buffers interleaved within each row).
    // Bs NT: same geometry (rows = n). Bs NN: 64 rows (buf*32+k) x 256B.
    __shared__ __align__(128) bf16 As[8192];
    __shared__ __align__(128) bf16 Bs[8192];

    const int tid  = threadIdx.x;
    const int lane = tid & 31;
    const int wid  = tid >> 5;
    const int wm   = wid >> 2;          // 0..1
    const int wn   = wid & 3;           // 0..3
    const int l7   = lane & 7;

    const int bx = blockIdx.x, by = blockIdx.y, bz = blockIdx.z;

    A += (long long)bz * sA + (long long)by * BM * K;
    long long cbase = (long long)bz * sC + (long long)by * BM * N + (long long)bx * BN;
    if (NT) B += (long long)bz * sB + (long long)bx * BN * K;
    else    B += (long long)bz * sB + bx * BN;

    const uint32_t sA0 = (uint32_t)__cvta_generic_to_shared(As);
    const uint32_t sB0 = (uint32_t)__cvta_generic_to_shared(Bs);

    float acc[4][4][4];
#pragma unroll
    for (int i = 0; i < 4; i++)
#pragma unroll
        for (int j = 0; j < 4; j++)
#pragma unroll
            for (int r = 0; r < 4; r++) acc[i][j][r] = 0.f;

    // ---- fragment address precompute ----
    // A: m = (lane>>3)&3 : rsel = bit3, ksel = bit4
    const int rowA  = wm * 64 + ((lane >> 3) & 1) * 8 + l7;
    const uint32_t aBase = sA0 + rowA * 128;
    const int tsA   = (((lane >> 4) & 1) ^ l7);
    // B NT: jsel = bit4, ksel = bit3
    const int rowB  = wn * 32 + ((lane >> 4) & 1) * 8 + l7;
    const uint32_t bBaseNT = sB0 + rowB * 128;
    const int tsB   = (((lane >> 3) & 1) ^ l7);
    // B NN (trans): ksel = bit3, jsel = bit4
    const uint32_t pBNN = (((lane >> 3) & 1) * 8 + l7) * 256;
    const int nu0   = wn * 4 + ((lane >> 4) & 1);
    const uint32_t offn0 = (uint32_t)((nu0 ^ l7) << 4);
    const uint32_t offn1 = (uint32_t)(((nu0 + 2) ^ l7) << 4);

    const int ntiles = K / BK;

    auto load_tile = [&](int buf, int k0) {
#pragma unroll
        for (int i = 0; i < 2; i++) {
            int idx = tid + i * 256;                 // 0..511
            int r = idx >> 2, u = idx & 3;
            uint32_t dst = sA0 + r * 128 + (uint32_t)(((((buf << 2) | u) ^ (r & 7))) << 4);
            cp16(dst, A + (long long)r * K + k0 + u * 8);
        }
        if (NT) {
#pragma unroll
            for (int i = 0; i < 2; i++) {
                int idx = tid + i * 256;
                int n = idx >> 2, u = idx & 3;
                uint32_t dst = sB0 + n * 128 + (uint32_t)(((((buf << 2) | u) ^ (n & 7))) << 4);
                cp16(dst, B + (long long)n * K + k0 + u * 8);
            }
        } else {
#pragma unroll
            for (int i = 0; i < 2; i++) {
                int idx = tid + i * 256;
                int k = idx >> 4, u = idx & 15;
                uint32_t dst = sB0 + (buf * 32 + k) * 256 + (uint32_t)((u ^ (k & 7)) << 4);
                cp16(dst, B + (long long)(k0 + k) * N + u * 8);
            }
        }
        asm volatile("cp.async.commit_group;");
    };

    load_tile(0, 0);
    int buf = 0;
    for (int t = 0; t < ntiles; t++) {
        if (t + 1 < ntiles) {
            load_tile(buf ^ 1, (t + 1) * BK);
            asm volatile("cp.async.wait_group 1;");
        } else {
            asm volatile("cp.async.wait_group 0;");
        }
        __syncthreads();

#pragma unroll
        for (int ks = 0; ks < 2; ks++) {
            const int cv = (buf << 2) | (ks << 1);
            uint32_t a[4][4], b[4][2];
#pragma unroll
            for (int i = 0; i < 4; i++)
                ldsm4(a[i], aBase + i * 2048 + (uint32_t)(((cv ^ tsA)) << 4));
            if (NT) {
                uint32_t t0[4], t1[4];
                ldsm4(t0, bBaseNT + 0 * 2048 + (uint32_t)((cv ^ tsB) << 4));
                ldsm4(t1, bBaseNT + 1 * 2048 + (uint32_t)((cv ^ tsB) << 4));
                b[0][0] = t0[0]; b[0][1] = t0[1]; b[1][0] = t0[2]; b[1][1] = t0[3];
                b[2][0] = t1[0]; b[2][1] = t1[1]; b[3][0] = t1[2]; b[3][1] = t1[3];
            } else {
                uint32_t t0[4], t1[4];
                uint32_t kb = sB0 + buf * 8192 + ks * 4096 + pBNN;
                ldsm4t(t0, kb + offn0);
                ldsm4t(t1, kb + offn1);
                b[0][0] = t0[0]; b[0][1] = t0[1]; b[1][0] = t0[2]; b[1][1] = t0[3];
                b[2][0] = t1[0]; b[2][1] = t1[1]; b[3][0] = t1[2]; b[3][1] = t1[3];
            }
#pragma unroll
            for (int i = 0; i < 4; i++)
#pragma unroll
                for (int j = 0; j < 4; j++)
                    mma16(acc[i][j], a[i], b[j]);
        }
        __syncthreads();
        buf ^= 1;
    }

    // ---- epilogue ----
    const int gr = lane >> 2, tg = lane & 3;
#pragma unroll
    for (int i = 0; i < 4; i++) {
        int r0 = wm * 64 + i * 16 + gr;
#pragma unroll
        for (int j = 0; j < 4; j++) {
            int col = wn * 32 + j * 8 + 2 * tg;
            float b0 = 0.f, b1 = 0.f;
            if (bias) {
                b0 = bias[bx * BN + col];
                b1 = bias[bx * BN + col + 1];
            }
            float v0 = acc[i][j][0] * scale + b0;
            float v1 = acc[i][j][1] * scale + b1;
            float v2 = acc[i][j][2] * scale + b0;
            float v3 = acc[i][j][3] * scale + b1;
            if (relu) {
                v0 = fmaxf(v0, 0.f); v1 = fmaxf(v1, 0.f);
                v2 = fmaxf(v2, 0.f); v3 = fmaxf(v3, 0.f);
            }
            if (OUTB) {
                bf16* C = (bf16*)Cv;
                __nv_bfloat162 p0, p1;
                p0.x = __float2bfloat16(v0); p0.y = __float2bfloat16(v1);
                p1.x = __float2bfloat16(v2); p1.y = __float2bfloat16(v3);
                *(__nv_bfloat162*)(C + cbase + (long long)r0 * N + col)       = p0;
                *(__nv_bfloat162*)(C + cbase + (long long)(r0 + 8) * N + col) = p1;
            } else {
                float* C = (float*)Cv;
                *(float2*)(C + cbase + (long long)r0 * N + col)       = make_float2(v0, v1);
                *(float2*)(C + cbase + (long long)(r0 + 8) * N + col) = make_float2(v2, v3);
            }
        }
    }
}

// ---------------- row softmax: f32 in, bf16 out, with pre-scale ----------------
__global__ __launch_bounds__(256)
void softmax_bf(const float* __restrict__ sc, bf16* __restrict__ pb, float scale)
{
    __shared__ float red[256];
    const long long row = blockIdx.x;
    const float* p = sc + row * (long long)S_;
    bf16* o = pb + row * (long long)S_;
    const int tid = threadIdx.x;

    float v[8];
    float m = -1e30f;
#pragma unroll
    for (int i = 0; i < 8; i++) {
        v[i] = p[tid + i * 256] * scale;
        m = fmaxf(m, v[i]);
    }
    red[tid] = m; __syncthreads();
    for (int o2 = 128; o2 > 0; o2 >>= 1) {
        if (tid < o2) red[tid] = fmaxf(red[tid], red[tid + o2]);
        __syncthreads();
    }
    m = red[0]; __syncthreads();

    float s = 0.f;
#pragma unroll
    for (int i = 0; i < 8; i++) { v[i] = expf(v[i] - m); s += v[i]; }
    red[tid] = s; __syncthreads();
    for (int o2 = 128; o2 > 0; o2 >>= 1) {
        if (tid < o2) red[tid] += red[tid + o2];
        __syncthreads();
    }
    float inv = 1.f / red[0];
#pragma unroll
    for (int i = 0; i < 8; i++)
        o[tid + i * 256] = __float2bfloat16(v[i] * inv);
}

// ---------------- residual + layernorm: x = LN(x + r), writes f32 + bf16 ----------------
__global__ __launch_bounds__(128)
void ln_kernel(float* __restrict__ x, bf16* __restrict__ xb,
               const float* __restrict__ r,
               const float* __restrict__ g, const float* __restrict__ b)
{
    __shared__ float red[128];
    const long long row = blockIdx.x;
    const int tid = threadIdx.x;
    float* px = x + row * (long long)D_;
    bf16* pb  = xb + row * (long long)D_;
    const float* pr = r + row * (long long)D_;

    float v[4];
    float s = 0.f;
#pragma unroll
    for (int i = 0; i < 4; i++) {
        v[i] = px[tid + i * 128] + pr[tid + i * 128];
        s += v[i];
    }
    red[tid] = s; __syncthreads();
    for (int o = 64; o > 0; o >>= 1) {
        if (tid < o) red[tid] += red[tid + o];
        __syncthreads();
    }
    const float mu = red[0] * (1.f / D_); __syncthreads();

    float sq = 0.f;
#pragma unroll
    for (int i = 0; i < 4; i++) { float d = v[i] - mu; sq += d * d; }
    red[tid] = sq; __syncthreads();
    for (int o = 64; o > 0; o >>= 1) {
        if (tid < o) red[tid] += red[tid + o];
        __syncthreads();
    }
    const float rstd = rsqrtf(red[0] * (1.f / D_) + 1e-5f);
#pragma unroll
    for (int i = 0; i < 4; i++) {
        int c = tid + i * 128;
        float y = (v[i] - mu) * rstd * g[c] + b[c];
        px[c] = y;
        pb[c] = __float2bfloat16(y);
    }
}

// ---------------- mean-pool over S then dot with clf_w ----------------
__global__ __launch_bounds__(256)
void pool_kernel(const float* __restrict__ x, const float* __restrict__ w,
                 const float* __restrict__ cb, float* __restrict__ out)
{
    __shared__ float red[256];
    const int b = blockIdx.x;
    const int tid = threadIdx.x;
    const float* p = x + (long long)b * S_ * D_;
    float acc = 0.f;
    for (int i = tid; i < S_ * D_; i += 256)
        acc += p[i] * w[i & (D_ - 1)];
    red[tid] = acc; __syncthreads();
    for (int o = 128; o > 0; o >>= 1) {
        if (tid < o) red[tid] += red[tid + o];
        __syncthreads();
    }
    if (tid == 0) out[b] = red[0] * (1.f / (float)S_) + cb[0];
}

// ---------------- host orchestration ----------------
extern "C" void kernel_launch(void* const* d_in, const int* in_sizes, int n_in,
                              void* d_out, int out_size)
{
    (void)in_sizes; (void)n_in; (void)out_size;
    const int*   tokens = (const int*)  d_in[0];
    const float* emb    = (const float*)d_in[1];
    const float* Wq     = (const float*)d_in[2];
    const float* bq     = (const float*)d_in[3];
    const float* Wk     = (const float*)d_in[4];
    const float* bk     = (const float*)d_in[5];
    const float* Wv     = (const float*)d_in[6];
    const float* bv     = (const float*)d_in[7];
    const float* Wo     = (const float*)d_in[8];
    const float* bo     = (const float*)d_in[9];
    const float* W1     = (const float*)d_in[10];
    const float* b1     = (const float*)d_in[11];
    const float* W2     = (const float*)d_in[12];
    const float* b2     = (const float*)d_in[13];
    const float* ln1g   = (const float*)d_in[14];
    const float* ln1b   = (const float*)d_in[15];
    const float* ln2g   = (const float*)d_in[16];
    const float* ln2b   = (const float*)d_in[17];
    const float* clfw   = (const float*)d_in[18];
    const float* clfb   = (const float*)d_in[19];
    float* out = (float*)d_out;

    float *x, *r, *sc;
    bf16 *xb, *qb, *kb, *vb, *tb, *hb, *pb;
    bf16 *wqb, *wkb, *wvb, *wob, *w1b, *w2b;
    cudaGetSymbolAddress((void**)&x,   g_x);
    cudaGetSymbolAddress((void**)&r,   g_r);
    cudaGetSymbolAddress((void**)&sc,  g_sc);
    cudaGetSymbolAddress((void**)&xb,  g_xb);
    cudaGetSymbolAddress((void**)&qb,  g_qb);
    cudaGetSymbolAddress((void**)&kb,  g_kb);
    cudaGetSymbolAddress((void**)&vb,  g_vb);
    cudaGetSymbolAddress((void**)&tb,  g_tb);
    cudaGetSymbolAddress((void**)&hb,  g_hb);
    cudaGetSymbolAddress((void**)&pb,  g_pb);
    cudaGetSymbolAddress((void**)&wqb, g_wqb);
    cudaGetSymbolAddress((void**)&wkb, g_wkb);
    cudaGetSymbolAddress((void**)&wvb, g_wvb);
    cudaGetSymbolAddress((void**)&wob, g_wob);
    cudaGetSymbolAddress((void**)&w1b, g_w1b);
    cudaGetSymbolAddress((void**)&w2b, g_w2b);

    // weight conversion (idempotent per launch)
    cvt_bf<<<(L_ * D_ * D_) / 256, 256>>>(Wq, wqb);
    cvt_bf<<<(L_ * D_ * D_) / 256, 256>>>(Wk, wkb);
    cvt_bf<<<(L_ * D_ * D_) / 256, 256>>>(Wv, wvb);
    cvt_bf<<<(L_ * D_ * D_) / 256, 256>>>(Wo, wob);
    cvt_bf<<<(L_ * D_ * F_) / 256, 256>>>(W1, w1b);
    cvt_bf<<<(L_ * D_ * F_) / 256, 256>>>(W2, w2b);

    embed_kernel<<<(BS_ * D_) / 256, 256>>>(tokens, emb, x, xb);

    const dim3 gProj(D_ / BN, BS_ / BM, 1);
    const dim3 gScores(S_ / BN, S_ / BM, B_);
    const dim3 gAV(D_ / BN, S_ / BM, B_);
    const dim3 gF1(F_ / BN, BS_ / BM, 1);
    const float kscale = 0.044194173824159216f;   // 1/sqrt(512)

    for (int l = 0; l < L_; l++) {
        const bf16* Wq_l = wqb + (size_t)l * D_ * D_;
        const bf16* Wk_l = wkb + (size_t)l * D_ * D_;
        const bf16* Wv_l = wvb + (size_t)l * D_ * D_;
        const bf16* Wo_l = wob + (size_t)l * D_ * D_;
        const bf16* W1_l = w1b + (size_t)l * D_ * F_;
        const bf16* W2_l = w2b + (size_t)l * F_ * D_;
        const float* bq_l = bq + (size_t)l * D_;
        const float* bk_l = bk + (size_t)l * D_;
        const float* bv_l = bv + (size_t)l * D_;
        const float* bo_l = bo + (size_t)l * D_;
        const float* b1_l = b1 + (size_t)l * F_;
        const float* b2_l = b2 + (size_t)l * D_;

        gemm_bf<0, 1><<<gProj, 256>>>(xb, Wq_l, bq_l, qb, BS_, D_, D_, 0, 0, 0, 1.f, 0);
        gemm_bf<0, 1><<<gProj, 256>>>(xb, Wk_l, bk_l, kb, BS_, D_, D_, 0, 0, 0, 1.f, 0);
        gemm_bf<0, 1><<<gProj, 256>>>(xb, Wv_l, bv_l, vb, BS_, D_, D_, 0, 0, 0, 1.f, 0);

        // scores[b] = q_b @ k_b^T (f32 out; scale applied in softmax)
        gemm_bf<1, 0><<<gScores, 256>>>(qb, kb, nullptr, sc, S_, S_, D_,
                                        (long long)S_ * D_, (long long)S_ * D_,
                                        (long long)S_ * S_, 1.f, 0);
        softmax_bf<<<B_ * S_, 256>>>(sc, pb, kscale);

        // t[b] = attn_b @ v_b   (bf16 out)
        gemm_bf<0, 1><<<gAV, 256>>>(pb, vb, nullptr, tb, S_, D_, S_,
                                    (long long)S_ * S_, (long long)S_ * D_,
                                    (long long)S_ * D_, 1.f, 0);

        // attn_out = t @ Wo + bo  (f32 out for residual)
        gemm_bf<0, 0><<<gProj, 256>>>(tb, Wo_l, bo_l, r, BS_, D_, D_, 0, 0, 0, 1.f, 0);
        ln_kernel<<<BS_, 128>>>(x, xb, r, ln1g + (size_t)l * D_, ln1b + (size_t)l * D_);

        // FFN
        gemm_bf<0, 1><<<gF1, 256>>>(xb, W1_l, b1_l, hb, BS_, F_, D_, 0, 0, 0, 1.f, 1);
        gemm_bf<0, 0><<<gProj, 256>>>(hb, W2_l, b2_l, r, BS_, D_, F_, 0, 0, 0, 1.f, 0);
        ln_kernel<<<BS_, 128>>>(x, xb, r, ln2g + (size_t)l * D_, ln2b + (size_t)l * D_);
    }

    pool_kernel<<<B_, 256>>>(x, clfw, clfb, out);
}

// round 7
// speedup vs baseline: 4.3698x; 1.0206x over previous
#include <cuda_runtime.h>
#include <cuda_bf16.h>
#include <cstdint>

typedef __nv_bfloat16 bf16;

#define D_  512
#define B_  8
#define S_  2048
#define F_  2048
#define L_  4
#define BS_ (B_*S_)

// ---------------- scratch (static device globals; no allocation) ----------------
__device__ __align__(256) float g_x [BS_*D_];            // f32 master activations
__device__ __align__(256) float g_r [BS_*D_];            // f32 residual branch
__device__ __align__(256) float g_sc[(size_t)B_*S_*S_];  // f32 attention scores
__device__ __align__(256) bf16  g_xb[BS_*D_];            // bf16 operand copies
__device__ __align__(256) bf16  g_qb[BS_*D_];
__device__ __align__(256) bf16  g_kb[BS_*D_];
__device__ __align__(256) bf16  g_vb[BS_*D_];
__device__ __align__(256) bf16  g_tb[BS_*D_];
__device__ __align__(256) bf16  g_hb[(size_t)BS_*F_];
__device__ __align__(256) bf16  g_pb[(size_t)B_*S_*S_];  // bf16 softmax probs
__device__ __align__(256) bf16  g_wqb[L_*D_*D_];
__device__ __align__(256) bf16  g_wkb[L_*D_*D_];
__device__ __align__(256) bf16  g_wvb[L_*D_*D_];
__device__ __align__(256) bf16  g_wob[L_*D_*D_];
__device__ __align__(256) bf16  g_w1b[(size_t)L_*D_*F_];
__device__ __align__(256) bf16  g_w2b[(size_t)L_*D_*F_];

// ---------------- f32 -> bf16 convert (weights) ----------------
__global__ void cvt_bf(const float* __restrict__ s, bf16* __restrict__ d)
{
    int i = blockIdx.x * 256 + threadIdx.x;
    d[i] = __float2bfloat16(s[i]);
}

// ---------------- embedding + sinusoidal PE (f32 + bf16 out) ----------------
__global__ void embed_kernel(const int* __restrict__ tok,
                             const float* __restrict__ emb,
                             float* __restrict__ x, bf16* __restrict__ xb)
{
    int idx = blockIdx.x * blockDim.x + threadIdx.x;
    int d  = idx & (D_ - 1);
    int bs = idx >> 9;
    int s  = bs & (S_ - 1);
    int t  = tok[bs];
    float dv  = expf(-(float)(d & ~1) * (9.210340371976184f / (float)D_));
    float arg = (float)s * dv;
    float pe  = (d & 1) ? cosf(arg) : sinf(arg);
    float v = emb[(size_t)t * D_ + d] + pe;
    x[idx]  = v;
    xb[idx] = __float2bfloat16(v);
}

// ---------------- bf16 tensor-core GEMM (256x128x64, 3-stage cp.async) ----------------
// C = scale*(A @ op(B)) [+bias] [relu]
// A: [M,K] bf16 row-major. NT=0: B [K,N] bf16 row-major. NT=1: B [N,K] bf16 (B^T).
// OUTB=1: C bf16; OUTB=0: C f32.
// 512 threads = 16 warps (4 M x 4 N), warp tile 64x32, m16n8k16 MMA, ldmatrix,
// XOR-swizzled smem, 3-stage cp.async pipeline.

#define BM 256
#define BN 128
#define BK 64
#define STAGES 3
#define A_STAGE_BYTES (BM * 128)           // 32768
#define B_STAGE_BYTES (16384)              // NT: 128 rows x 128B; NN: 64 rows x 256B
#define SMEM_BYTES (STAGES * (A_STAGE_BYTES + B_STAGE_BYTES))   // 147456

__device__ __forceinline__ void cp16(uint32_t dst, const void* src) {
    asm volatile("cp.async.cg.shared.global [%0], [%1], 16;" :: "r"(dst), "l"(src));
}
__device__ __forceinline__ void ldsm4(uint32_t* r, uint32_t addr) {
    asm volatile("ldmatrix.sync.aligned.m8n8.x4.shared.b16 {%0,%1,%2,%3}, [%4];"
        : "=r"(r[0]), "=r"(r[1]), "=r"(r[2]), "=r"(r[3]) : "r"(addr));
}
__device__ __forceinline__ void ldsm4t(uint32_t* r, uint32_t addr) {
    asm volatile("ldmatrix.sync.aligned.m8n8.x4.trans.shared.b16 {%0,%1,%2,%3}, [%4];"
        : "=r"(r[0]), "=r"(r[1]), "=r"(r[2]), "=r"(r[3]) : "r"(addr));
}
__device__ __forceinline__ void mma16(float* c, const uint32_t* a, const uint32_t* b) {
    asm volatile(
        "mma.sync.aligned.m16n8k16.row.col.f32.bf16.bf16.f32 "
        "{%0,%1,%2,%3},{%4,%5,%6,%7},{%8,%9},{%0,%1,%2,%3};"
        : "+f"(c[0]), "+f"(c[1]), "+f"(c[2]), "+f"(c[3])
        : "r"(a[0]), "r"(a[1]), "r"(a[2]), "r"(a[3]), "r"(b[0]), "r"(b[1]));
}

template<int NT, int OUTB>
__global__ __launch_bounds__(512, 1)
void gemm_bf(const bf16* __restrict__ A, const bf16* __restrict__ B,
             const float* __restrict__ bias, void* __restrict__ Cv,
             int M, int N, int K,
             long long sA, long long sB, long long sC,
             float scale, int relu)
{
    extern __shared__ __align__(128) char smem[];

    const int tid  = threadIdx.x;
    const int lane = tid & 31;
    const int wid  = tid >> 5;
    const int wm   = wid >> 2;          // 0..3 (M dir, 64 rows each)
    const int wn   = wid & 3;           // 0..3 (N dir, 32 cols each)
    const int l7   = lane & 7;

    const int bx = blockIdx.x, by = blockIdx.y, bz = blockIdx.z;

    A += (long long)bz * sA + (long long)by * BM * K;
    long long cbase = (long long)bz * sC + (long long)by * BM * N + (long long)bx * BN;
    if (NT) B += (long long)bz * sB + (long long)bx * BN * K;
    else    B += (long long)bz * sB + bx * BN;

    const uint32_t sA0 = (uint32_t)__cvta_generic_to_shared(smem);
    const uint32_t sB0 = sA0 + STAGES * A_STAGE_BYTES;

    float acc[4][4][4];
#pragma unroll
    for (int i = 0; i < 4; i++)
#pragma unroll
        for (int j = 0; j < 4; j++)
#pragma unroll
            for (int r = 0; r < 4; r++) acc[i][j][r] = 0.f;

    // ---- fragment address precompute ----
    const int rowA0 = wm * 64 + ((lane >> 3) & 1) * 8 + l7;   // rowA0 & 7 == l7
    const int khA   = (lane >> 4) & 1;
    const int rowB0 = wn * 32 + ((lane >> 4) & 1) * 8 + l7;   // NT; rowB0 & 7 == l7
    const int khB   = (lane >> 3) & 1;
    const int krow0 = ((lane >> 3) & 1) * 8 + l7;             // NN (trans)
    const int nu0   = wn * 4 + ((lane >> 4) & 1);

    const int kt = K / BK;

    auto load_tile = [&](int stg, int k0) {
        uint32_t aS = sA0 + stg * A_STAGE_BYTES;
#pragma unroll
        for (int i = 0; i < 4; i++) {
            int idx = tid + i * 512;                 // 0..2047
            int r = idx >> 3, u = idx & 7;
            cp16(aS + r * 128 + (uint32_t)((u ^ (r & 7)) << 4),
                 A + (long long)r * K + k0 + u * 8);
        }
        uint32_t bS = sB0 + stg * B_STAGE_BYTES;
        if (NT) {
#pragma unroll
            for (int i = 0; i < 2; i++) {
                int idx = tid + i * 512;             // 0..1023
                int n = idx >> 3, u = idx & 7;
                cp16(bS + n * 128 + (uint32_t)((u ^ (n & 7)) << 4),
                     B + (long long)n * K + k0 + u * 8);
            }
        } else {
#pragma unroll
            for (int i = 0; i < 2; i++) {
                int idx = tid + i * 512;
                int k = idx >> 4, u = idx & 15;
                cp16(bS + k * 256 + (uint32_t)((u ^ (k & 7)) << 4),
                     B + (long long)(k0 + k) * N + u * 8);
            }
        }
        asm volatile("cp.async.commit_group;");
    };

    // prologue: fill stages 0 and 1
    load_tile(0, 0);
    load_tile(1, BK);

    int stg = 0;
    for (int t = 0; t < kt; t++) {
        if (t == kt - 1) asm volatile("cp.async.wait_group 0;");
        else             asm volatile("cp.async.wait_group 1;");
        __syncthreads();

        if (t + 2 < kt) load_tile((t + 2) % STAGES, (t + 2) * BK);

        const uint32_t aS = sA0 + stg * A_STAGE_BYTES;
        const uint32_t bS = sB0 + stg * B_STAGE_BYTES;
        const uint32_t aFrag = aS + rowA0 * 128;
        const uint32_t bFragNT = bS + rowB0 * 128;

#pragma unroll
        for (int ks = 0; ks < 4; ks++) {
            uint32_t a[4][4], b[4][2];
            const uint32_t auoff = (uint32_t)(((2 * ks + khA) ^ l7) << 4);
#pragma unroll
            for (int i = 0; i < 4; i++)
                ldsm4(a[i], aFrag + i * 2048 + auoff);
            if (NT) {
                const uint32_t buoff = (uint32_t)(((2 * ks + khB) ^ l7) << 4);
                uint32_t t0[4], t1[4];
                ldsm4(t0, bFragNT + buoff);
                ldsm4(t1, bFragNT + 2048 + buoff);
                b[0][0] = t0[0]; b[0][1] = t0[1]; b[1][0] = t0[2]; b[1][1] = t0[3];
                b[2][0] = t1[0]; b[2][1] = t1[1]; b[3][0] = t1[2]; b[3][1] = t1[3];
            } else {
                uint32_t t0[4], t1[4];
                uint32_t kb = bS + (ks * 16 + krow0) * 256;
                ldsm4t(t0, kb + (uint32_t)((nu0 ^ l7) << 4));
                ldsm4t(t1, kb + (uint32_t)(((nu0 + 2) ^ l7) << 4));
                b[0][0] = t0[0]; b[0][1] = t0[1]; b[1][0] = t0[2]; b[1][1] = t0[3];
                b[2][0] = t1[0]; b[2][1] = t1[1]; b[3][0] = t1[2]; b[3][1] = t1[3];
            }
#pragma unroll
            for (int i = 0; i < 4; i++)
#pragma unroll
                for (int j = 0; j < 4; j++)
                    mma16(acc[i][j], a[i], b[j]);
        }
        __syncthreads();
        stg = (stg + 1 == STAGES) ? 0 : stg + 1;
    }

    // ---- epilogue ----
    const int gr = lane >> 2, tg = lane & 3;
#pragma unroll
    for (int i = 0; i < 4; i++) {
        int r0 = wm * 64 + i * 16 + gr;
#pragma unroll
        for (int j = 0; j < 4; j++) {
            int col = wn * 32 + j * 8 + 2 * tg;
            float b0 = 0.f, b1 = 0.f;
            if (bias) {
                b0 = bias[bx * BN + col];
                b1 = bias[bx * BN + col + 1];
            }
            float v0 = acc[i][j][0] * scale + b0;
            float v1 = acc[i][j][1] * scale + b1;
            float v2 = acc[i][j][2] * scale + b0;
            float v3 = acc[i][j][3] * scale + b1;
            if (relu) {
                v0 = fmaxf(v0, 0.f); v1 = fmaxf(v1, 0.f);
                v2 = fmaxf(v2, 0.f); v3 = fmaxf(v3, 0.f);
            }
            if (OUTB) {
                bf16* C = (bf16*)Cv;
                __nv_bfloat162 p0, p1;
                p0.x = __float2bfloat16(v0); p0.y = __float2bfloat16(v1);
                p1.x = __float2bfloat16(v2); p1.y = __float2bfloat16(v3);
                *(__nv_bfloat162*)(C + cbase + (long long)r0 * N + col)       = p0;
                *(__nv_bfloat162*)(C + cbase + (long long)(r0 + 8) * N + col) = p1;
            } else {
                float* C = (float*)Cv;
                *(float2*)(C + cbase + (long long)r0 * N + col)       = make_float2(v0, v1);
                *(float2*)(C + cbase + (long long)(r0 + 8) * N + col) = make_float2(v2, v3);
            }
        }
    }
}

// ---------------- row softmax: f32 in, bf16 out, with pre-scale ----------------
__global__ __launch_bounds__(256)
void softmax_bf(const float* __restrict__ sc, bf16* __restrict__ pb, float scale)
{
    __shared__ float red[256];
    const long long row = blockIdx.x;
    const float* p = sc + row * (long long)S_;
    bf16* o = pb + row * (long long)S_;
    const int tid = threadIdx.x;

    float v[8];
    float m = -1e30f;
#pragma unroll
    for (int i = 0; i < 8; i++) {
        v[i] = p[tid + i * 256] * scale;
        m = fmaxf(m, v[i]);
    }
    red[tid] = m; __syncthreads();
    for (int o2 = 128; o2 > 0; o2 >>= 1) {
        if (tid < o2) red[tid] = fmaxf(red[tid], red[tid + o2]);
        __syncthreads();
    }
    m = red[0]; __syncthreads();

    float s = 0.f;
#pragma unroll
    for (int i = 0; i < 8; i++) { v[i] = expf(v[i] - m); s += v[i]; }
    red[tid] = s; __syncthreads();
    for (int o2 = 128; o2 > 0; o2 >>= 1) {
        if (tid < o2) red[tid] += red[tid + o2];
        __syncthreads();
    }
    float inv = 1.f / red[0];
#pragma unroll
    for (int i = 0; i < 8; i++)
        o[tid + i * 256] = __float2bfloat16(v[i] * inv);
}

// ---------------- residual + layernorm: x = LN(x + r), writes f32 + bf16 ----------------
__global__ __launch_bounds__(128)
void ln_kernel(float* __restrict__ x, bf16* __restrict__ xb,
               const float* __restrict__ r,
               const float* __restrict__ g, const float* __restrict__ b)
{
    __shared__ float red[128];
    const long long row = blockIdx.x;
    const int tid = threadIdx.x;
    float* px = x + row * (long long)D_;
    bf16* pb  = xb + row * (long long)D_;
    const float* pr = r + row * (long long)D_;

    float v[4];
    float s = 0.f;
#pragma unroll
    for (int i = 0; i < 4; i++) {
        v[i] = px[tid + i * 128] + pr[tid + i * 128];
        s += v[i];
    }
    red[tid] = s; __syncthreads();
    for (int o = 64; o > 0; o >>= 1) {
        if (tid < o) red[tid] += red[tid + o];
        __syncthreads();
    }
    const float mu = red[0] * (1.f / D_); __syncthreads();

    float sq = 0.f;
#pragma unroll
    for (int i = 0; i < 4; i++) { float d = v[i] - mu; sq += d * d; }
    red[tid] = sq; __syncthreads();
    for (int o = 64; o > 0; o >>= 1) {
        if (tid < o) red[tid] += red[tid + o];
        __syncthreads();
    }
    const float rstd = rsqrtf(red[0] * (1.f / D_) + 1e-5f);
#pragma unroll
    for (int i = 0; i < 4; i++) {
        int c = tid + i * 128;
        float y = (v[i] - mu) * rstd * g[c] + b[c];
        px[c] = y;
        pb[c] = __float2bfloat16(y);
    }
}

// ---------------- mean-pool over S then dot with clf_w ----------------
__global__ __launch_bounds__(256)
void pool_kernel(const float* __restrict__ x, const float* __restrict__ w,
                 const float* __restrict__ cb, float* __restrict__ out)
{
    __shared__ float red[256];
    const int b = blockIdx.x;
    const int tid = threadIdx.x;
    const float* p = x + (long long)b * S_ * D_;
    float acc = 0.f;
    for (int i = tid; i < S_ * D_; i += 256)
        acc += p[i] * w[i & (D_ - 1)];
    red[tid] = acc; __syncthreads();
    for (int o = 128; o > 0; o >>= 1) {
        if (tid < o) red[tid] += red[tid + o];
        __syncthreads();
    }
    if (tid == 0) out[b] = red[0] * (1.f / (float)S_) + cb[0];
}

// ---------------- host orchestration ----------------
extern "C" void kernel_launch(void* const* d_in, const int* in_sizes, int n_in,
                              void* d_out, int out_size)
{
    (void)in_sizes; (void)n_in; (void)out_size;
    const int*   tokens = (const int*)  d_in[0];
    const float* emb    = (const float*)d_in[1];
    const float* Wq     = (const float*)d_in[2];
    const float* bq     = (const float*)d_in[3];
    const float* Wk     = (const float*)d_in[4];
    const float* bk     = (const float*)d_in[5];
    const float* Wv     = (const float*)d_in[6];
    const float* bv     = (const float*)d_in[7];
    const float* Wo     = (const float*)d_in[8];
    const float* bo     = (const float*)d_in[9];
    const float* W1     = (const float*)d_in[10];
    const float* b1     = (const float*)d_in[11];
    const float* W2     = (const float*)d_in[12];
    const float* b2     = (const float*)d_in[13];
    const float* ln1g   = (const float*)d_in[14];
    const float* ln1b   = (const float*)d_in[15];
    const float* ln2g   = (const float*)d_in[16];
    const float* ln2b   = (const float*)d_in[17];
    const float* clfw   = (const float*)d_in[18];
    const float* clfb   = (const float*)d_in[19];
    float* out = (float*)d_out;

    float *x, *r, *sc;
    bf16 *xb, *qb, *kb, *vb, *tb, *hb, *pb;
    bf16 *wqb, *wkb, *wvb, *wob, *w1b, *w2b;
    cudaGetSymbolAddress((void**)&x,   g_x);
    cudaGetSymbolAddress((void**)&r,   g_r);
    cudaGetSymbolAddress((void**)&sc,  g_sc);
    cudaGetSymbolAddress((void**)&xb,  g_xb);
    cudaGetSymbolAddress((void**)&qb,  g_qb);
    cudaGetSymbolAddress((void**)&kb,  g_kb);
    cudaGetSymbolAddress((void**)&vb,  g_vb);
    cudaGetSymbolAddress((void**)&tb,  g_tb);
    cudaGetSymbolAddress((void**)&hb,  g_hb);
    cudaGetSymbolAddress((void**)&pb,  g_pb);
    cudaGetSymbolAddress((void**)&wqb, g_wqb);
    cudaGetSymbolAddress((void**)&wkb, g_wkb);
    cudaGetSymbolAddress((void**)&wvb, g_wvb);
    cudaGetSymbolAddress((void**)&wob, g_wob);
    cudaGetSymbolAddress((void**)&w1b, g_w1b);
    cudaGetSymbolAddress((void**)&w2b, g_w2b);

    // allow 147KB dynamic smem on the GEMM instantiations (idempotent)
    cudaFuncSetAttribute(gemm_bf<0,1>, cudaFuncAttributeMaxDynamicSharedMemorySize, SMEM_BYTES);
    cudaFuncSetAttribute(gemm_bf<0,0>, cudaFuncAttributeMaxDynamicSharedMemorySize, SMEM_BYTES);
    cudaFuncSetAttribute(gemm_bf<1,0>, cudaFuncAttributeMaxDynamicSharedMemorySize, SMEM_BYTES);

    // weight conversion (idempotent per launch)
    cvt_bf<<<(L_ * D_ * D_) / 256, 256>>>(Wq, wqb);
    cvt_bf<<<(L_ * D_ * D_) / 256, 256>>>(Wk, wkb);
    cvt_bf<<<(L_ * D_ * D_) / 256, 256>>>(Wv, wvb);
    cvt_bf<<<(L_ * D_ * D_) / 256, 256>>>(Wo, wob);
    cvt_bf<<<(L_ * D_ * F_) / 256, 256>>>(W1, w1b);
    cvt_bf<<<(L_ * D_ * F_) / 256, 256>>>(W2, w2b);

    embed_kernel<<<(BS_ * D_) / 256, 256>>>(tokens, emb, x, xb);

    const dim3 gProj(D_ / BN, BS_ / BM, 1);      // 4 x 64
    const dim3 gScores(S_ / BN, S_ / BM, B_);    // 16 x 8 x 8
    const dim3 gAV(D_ / BN, S_ / BM, B_);        // 4 x 8 x 8
    const dim3 gF1(F_ / BN, BS_ / BM, 1);        // 16 x 64
    const float kscale = 0.044194173824159216f;  // 1/sqrt(512)

    for (int l = 0; l < L_; l++) {
        const bf16* Wq_l = wqb + (size_t)l * D_ * D_;
        const bf16* Wk_l = wkb + (size_t)l * D_ * D_;
        const bf16* Wv_l = wvb + (size_t)l * D_ * D_;
        const bf16* Wo_l = wob + (size_t)l * D_ * D_;
        const bf16* W1_l = w1b + (size_t)l * D_ * F_;
        const bf16* W2_l = w2b + (size_t)l * F_ * D_;
        const float* bq_l = bq + (size_t)l * D_;
        const float* bk_l = bk + (size_t)l * D_;
        const float* bv_l = bv + (size_t)l * D_;
        const float* bo_l = bo + (size_t)l * D_;
        const float* b1_l = b1 + (size_t)l * F_;
        const float* b2_l = b2 + (size_t)l * D_;

        gemm_bf<0, 1><<<gProj, 512, SMEM_BYTES>>>(xb, Wq_l, bq_l, qb, BS_, D_, D_, 0, 0, 0, 1.f, 0);
        gemm_bf<0, 1><<<gProj, 512, SMEM_BYTES>>>(xb, Wk_l, bk_l, kb, BS_, D_, D_, 0, 0, 0, 1.f, 0);
        gemm_bf<0, 1><<<gProj, 512, SMEM_BYTES>>>(xb, Wv_l, bv_l, vb, BS_, D_, D_, 0, 0, 0, 1.f, 0);

        // scores[b] = q_b @ k_b^T (f32 out; scale applied in softmax)
        gemm_bf<1, 0><<<gScores, 512, SMEM_BYTES>>>(qb, kb, nullptr, sc, S_, S_, D_,
                                        (long long)S_ * D_, (long long)S_ * D_,
                                        (long long)S_ * S_, 1.f, 0);
        softmax_bf<<<B_ * S_, 256>>>(sc, pb, kscale);

        // t[b] = attn_b @ v_b   (bf16 out)
        gemm_bf<0, 1><<<gAV, 512, SMEM_BYTES>>>(pb, vb, nullptr, tb, S_, D_, S_,
                                    (long long)S_ * S_, (long long)S_ * D_,
                                    (long long)S_ * D_, 1.f, 0);

        // attn_out = t @ Wo + bo  (f32 out for residual)
        gemm_bf<0, 0><<<gProj, 512, SMEM_BYTES>>>(tb, Wo_l, bo_l, r, BS_, D_, D_, 0, 0, 0, 1.f, 0);
        ln_kernel<<<BS_, 128>>>(x, xb, r, ln1g + (size_t)l * D_, ln1b + (size_t)l * D_);

        // FFN
        gemm_bf<0, 1><<<gF1, 512, SMEM_BYTES>>>(xb, W1_l, b1_l, hb, BS_, F_, D_, 0, 0, 0, 1.f, 1);
        gemm_bf<0, 0><<<gProj, 512, SMEM_BYTES>>>(hb, W2_l, b2_l, r, BS_, D_, F_, 0, 0, 0, 1.f, 0);
        ln_kernel<<<BS_, 128>>>(x, xb, r, ln2g + (size_t)l * D_, ln2b + (size_t)l * D_);
    }

    pool_kernel<<<B_, 256>>>(x, clfw, clfb, out);
}

// round 12
// speedup vs baseline: 6.6511x; 1.5220x over previous
#include <cuda_runtime.h>
#include <cuda_bf16.h>
#include <cstdint>

typedef __nv_bfloat16 bf16;

#define D_  512
#define B_  8
#define S_  2048
#define F_  2048
#define L_  4
#define BS_ (B_*S_)

// ---------------- scratch (static device globals; no allocation) ----------------
__device__ __align__(256) float g_x [BS_*D_];            // f32 master activations
__device__ __align__(256) float g_r [BS_*D_];            // f32 residual branch
__device__ __align__(256) float g_sc[(size_t)B_*S_*S_];  // f32 attention scores
__device__ __align__(256) bf16  g_xb[BS_*D_];            // bf16 operand copies
__device__ __align__(256) bf16  g_qb[BS_*D_];
__device__ __align__(256) bf16  g_kb[BS_*D_];
__device__ __align__(256) bf16  g_vb[BS_*D_];
__device__ __align__(256) bf16  g_tb[BS_*D_];
__device__ __align__(256) bf16  g_hb[(size_t)BS_*F_];
__device__ __align__(256) bf16  g_pb[(size_t)B_*S_*S_];  // bf16 softmax probs
__device__ __align__(256) bf16  g_wqb[L_*D_*D_];
__device__ __align__(256) bf16  g_wkb[L_*D_*D_];
__device__ __align__(256) bf16  g_wvb[L_*D_*D_];
__device__ __align__(256) bf16  g_wob[L_*D_*D_];
__device__ __align__(256) bf16  g_w1b[(size_t)L_*D_*F_];
__device__ __align__(256) bf16  g_w2b[(size_t)L_*D_*F_];

// ---------------- f32 -> bf16 convert (weights) ----------------
__global__ void cvt_bf(const float* __restrict__ s, bf16* __restrict__ d)
{
    int i = blockIdx.x * 256 + threadIdx.x;
    d[i] = __float2bfloat16(s[i]);
}

// ---------------- embedding + sinusoidal PE (f32 + bf16 out) ----------------
__global__ void embed_kernel(const int* __restrict__ tok,
                             const float* __restrict__ emb,
                             float* __restrict__ x, bf16* __restrict__ xb)
{
    int idx = blockIdx.x * blockDim.x + threadIdx.x;
    int d  = idx & (D_ - 1);
    int bs = idx >> 9;
    int s  = bs & (S_ - 1);
    int t  = tok[bs];
    float dv  = expf(-(float)(d & ~1) * (9.210340371976184f / (float)D_));
    float arg = (float)s * dv;
    float pe  = (d & 1) ? cosf(arg) : sinf(arg);
    float v = emb[(size_t)t * D_ + d] + pe;
    x[idx]  = v;
    xb[idx] = __float2bfloat16(v);
}

// ---------------- bf16 tensor-core GEMM (128x256x64, 3-stage cp.async) ----------------
// C = scale*(A @ op(B)) [+bias] [relu]
// A: [M,K] bf16 row-major. NT=0: B [K,N] bf16 row-major. NT=1: B [N,K] bf16 (B^T).
// OUTB=1: C bf16; OUTB=0: C f32.
// 256 threads = 8 warps (2 M x 4 N), warp tile 64x64, m16n8k16 MMA, ldmatrix,
// XOR-swizzled smem, 3-stage cp.async pipeline.

#define BM 128
#define BN 256
#define BK 64
#define STAGES 3
#define A_STAGE_BYTES (BM * 128)                  // 16384
#define B_STAGE_BYTES 32768                       // NT: 256 rows x 128B; NN: 64 rows x 512B
#define STG_BYTES (A_STAGE_BYTES + B_STAGE_BYTES) // 49152
#define SMEM_BYTES (STAGES * STG_BYTES)           // 147456

__device__ __forceinline__ void cp16(uint32_t dst, const void* src) {
    asm volatile("cp.async.cg.shared.global [%0], [%1], 16;" :: "r"(dst), "l"(src));
}
__device__ __forceinline__ void ldsm4(uint32_t* r, uint32_t addr) {
    asm volatile("ldmatrix.sync.aligned.m8n8.x4.shared.b16 {%0,%1,%2,%3}, [%4];"
        : "=r"(r[0]), "=r"(r[1]), "=r"(r[2]), "=r"(r[3]) : "r"(addr));
}
__device__ __forceinline__ void ldsm4t(uint32_t* r, uint32_t addr) {
    asm volatile("ldmatrix.sync.aligned.m8n8.x4.trans.shared.b16 {%0,%1,%2,%3}, [%4];"
        : "=r"(r[0]), "=r"(r[1]), "=r"(r[2]), "=r"(r[3]) : "r"(addr));
}
__device__ __forceinline__ void mma16(float* c, const uint32_t* a, const uint32_t* b) {
    asm volatile(
        "mma.sync.aligned.m16n8k16.row.col.f32.bf16.bf16.f32 "
        "{%0,%1,%2,%3},{%4,%5,%6,%7},{%8,%9},{%0,%1,%2,%3};"
        : "+f"(c[0]), "+f"(c[1]), "+f"(c[2]), "+f"(c[3])
        : "r"(a[0]), "r"(a[1]), "r"(a[2]), "r"(a[3]), "r"(b[0]), "r"(b[1]));
}

template<int NT, int OUTB>
__global__ __launch_bounds__(256, 1)
void gemm_bf(const bf16* __restrict__ A, const bf16* __restrict__ B,
             const float* __restrict__ bias, void* __restrict__ Cv,
             int M, int N, int K,
             long long sA, long long sB, long long sC,
             float scale, int relu)
{
    extern __shared__ __align__(128) char smem[];

    const int tid  = threadIdx.x;
    const int lane = tid & 31;
    const int wid  = tid >> 5;
    const int wm   = wid >> 2;          // 0..1 (M dir, 64 rows each)
    const int wn   = wid & 3;           // 0..3 (N dir, 64 cols each)
    const int l7   = lane & 7;

    const int bx = blockIdx.x, by = blockIdx.y, bz = blockIdx.z;

    A += (long long)bz * sA + (long long)by * BM * K;
    long long cbase = (long long)bz * sC + (long long)by * BM * N + (long long)bx * BN;
    if (NT) B += (long long)bz * sB + (long long)bx * BN * K;
    else    B += (long long)bz * sB + bx * BN;

    const uint32_t sA0 = (uint32_t)__cvta_generic_to_shared(smem);
    const uint32_t sB0 = sA0 + STAGES * A_STAGE_BYTES;

    float acc[4][8][4];
#pragma unroll
    for (int i = 0; i < 4; i++)
#pragma unroll
        for (int j = 0; j < 8; j++)
#pragma unroll
            for (int r = 0; r < 4; r++) acc[i][j][r] = 0.f;

    // ---- fragment address precompute (same scheme as verified R7 kernel) ----
    const int rowA0 = wm * 64 + ((lane >> 3) & 1) * 8 + l7;   // rowA0 & 7 == l7
    const int khA   = (lane >> 4) & 1;
    const int rowB0 = wn * 64 + ((lane >> 4) & 1) * 8 + l7;   // NT; rowB0 & 7 == l7
    const int khB   = (lane >> 3) & 1;
    const int krow0 = ((lane >> 3) & 1) * 8 + l7;             // NN (trans)
    const int nu0   = wn * 8 + ((lane >> 4) & 1);             // 16B n-unit within 512B row

    const int kt = K / BK;

    auto load_tile = [&](int stg, int k0) {
        uint32_t aS = sA0 + stg * A_STAGE_BYTES;
#pragma unroll
        for (int i = 0; i < 4; i++) {
            int idx = tid + i * 256;                 // 0..1023
            int r = idx >> 3, u = idx & 7;
            cp16(aS + r * 128 + (uint32_t)((u ^ (r & 7)) << 4),
                 A + (long long)r * K + k0 + u * 8);
        }
        uint32_t bS = sB0 + stg * B_STAGE_BYTES;
        if (NT) {
#pragma unroll
            for (int i = 0; i < 8; i++) {
                int idx = tid + i * 256;             // 0..2047
                int n = idx >> 3, u = idx & 7;
                cp16(bS + n * 128 + (uint32_t)((u ^ (n & 7)) << 4),
                     B + (long long)n * K + k0 + u * 8);
            }
        } else {
#pragma unroll
            for (int i = 0; i < 8; i++) {
                int idx = tid + i * 256;             // 0..2047
                int k = idx >> 5, u = idx & 31;
                cp16(bS + k * 512 + (uint32_t)((u ^ (k & 7)) << 4),
                     B + (long long)(k0 + k) * N + u * 8);
            }
        }
        asm volatile("cp.async.commit_group;");
    };

    // prologue: fill stages 0 and 1
    load_tile(0, 0);
    load_tile(1, BK);

    int stg = 0;
    for (int t = 0; t < kt; t++) {
        if (t == kt - 1) asm volatile("cp.async.wait_group 0;");
        else             asm volatile("cp.async.wait_group 1;");
        __syncthreads();

        if (t + 2 < kt) load_tile((t + 2) % STAGES, (t + 2) * BK);

        const uint32_t aS = sA0 + stg * A_STAGE_BYTES;
        const uint32_t bS = sB0 + stg * B_STAGE_BYTES;
        const uint32_t aFrag = aS + rowA0 * 128;
        const uint32_t bFragNT = bS + rowB0 * 128;

#pragma unroll
        for (int ks = 0; ks < 4; ks++) {
            uint32_t a[4][4], b[8][2];
            const uint32_t auoff = (uint32_t)(((2 * ks + khA) ^ l7) << 4);
#pragma unroll
            for (int i = 0; i < 4; i++)
                ldsm4(a[i], aFrag + i * 2048 + auoff);
            if (NT) {
                const uint32_t buoff = (uint32_t)(((2 * ks + khB) ^ l7) << 4);
#pragma unroll
                for (int jb = 0; jb < 4; jb++) {
                    uint32_t t0[4];
                    ldsm4(t0, bFragNT + jb * 2048 + buoff);
                    b[2 * jb][0] = t0[0]; b[2 * jb][1] = t0[1];
                    b[2 * jb + 1][0] = t0[2]; b[2 * jb + 1][1] = t0[3];
                }
            } else {
                uint32_t kb = bS + (ks * 16 + krow0) * 512;
#pragma unroll
                for (int jb = 0; jb < 4; jb++) {
                    uint32_t t0[4];
                    ldsm4t(t0, kb + (uint32_t)(((nu0 + 2 * jb) ^ l7) << 4));
                    b[2 * jb][0] = t0[0]; b[2 * jb][1] = t0[1];
                    b[2 * jb + 1][0] = t0[2]; b[2 * jb + 1][1] = t0[3];
                }
            }
#pragma unroll
            for (int i = 0; i < 4; i++)
#pragma unroll
                for (int j = 0; j < 8; j++)
                    mma16(acc[i][j], a[i], b[j]);
        }
        __syncthreads();
        stg = (stg + 1 == STAGES) ? 0 : stg + 1;
    }

    // ---- epilogue ----
    const int gr = lane >> 2, tg = lane & 3;
#pragma unroll
    for (int i = 0; i < 4; i++) {
        int r0 = wm * 64 + i * 16 + gr;
#pragma unroll
        for (int j = 0; j < 8; j++) {
            int col = wn * 64 + j * 8 + 2 * tg;
            float b0 = 0.f, b1 = 0.f;
            if (bias) {
                b0 = bias[bx * BN + col];
                b1 = bias[bx * BN + col + 1];
            }
            float v0 = acc[i][j][0] * scale + b0;
            float v1 = acc[i][j][1] * scale + b1;
            float v2 = acc[i][j][2] * scale + b0;
            float v3 = acc[i][j][3] * scale + b1;
            if (relu) {
                v0 = fmaxf(v0, 0.f); v1 = fmaxf(v1, 0.f);
                v2 = fmaxf(v2, 0.f); v3 = fmaxf(v3, 0.f);
            }
            if (OUTB) {
                bf16* C = (bf16*)Cv;
                __nv_bfloat162 p0, p1;
                p0.x = __float2bfloat16(v0); p0.y = __float2bfloat16(v1);
                p1.x = __float2bfloat16(v2); p1.y = __float2bfloat16(v3);
                *(__nv_bfloat162*)(C + cbase + (long long)r0 * N + col)       = p0;
                *(__nv_bfloat162*)(C + cbase + (long long)(r0 + 8) * N + col) = p1;
            } else {
                float* C = (float*)Cv;
                *(float2*)(C + cbase + (long long)r0 * N + col)       = make_float2(v0, v1);
                *(float2*)(C + cbase + (long long)(r0 + 8) * N + col) = make_float2(v2, v3);
            }
        }
    }
}

// ---------------- row softmax: f32 in, bf16 out, with pre-scale ----------------
__global__ __launch_bounds__(256)
void softmax_bf(const float* __restrict__ sc, bf16* __restrict__ pb, float scale)
{
    __shared__ float red[256];
    const long long row = blockIdx.x;
    const float* p = sc + row * (long long)S_;
    bf16* o = pb + row * (long long)S_;
    const int tid = threadIdx.x;

    float v[8];
    float m = -1e30f;
#pragma unroll
    for (int i = 0; i < 8; i++) {
        v[i] = p[tid + i * 256] * scale;
        m = fmaxf(m, v[i]);
    }
    red[tid] = m; __syncthreads();
    for (int o2 = 128; o2 > 0; o2 >>= 1) {
        if (tid < o2) red[tid] = fmaxf(red[tid], red[tid + o2]);
        __syncthreads();
    }
    m = red[0]; __syncthreads();

    float s = 0.f;
#pragma unroll
    for (int i = 0; i < 8; i++) { v[i] = expf(v[i] - m); s += v[i]; }
    red[tid] = s; __syncthreads();
    for (int o2 = 128; o2 > 0; o2 >>= 1) {
        if (tid < o2) red[tid] += red[tid + o2];
        __syncthreads();
    }
    float inv = 1.f / red[0];
#pragma unroll
    for (int i = 0; i < 8; i++)
        o[tid + i * 256] = __float2bfloat16(v[i] * inv);
}

// ---------------- residual + layernorm: x = LN(x + r), writes f32 + bf16 ----------------
__global__ __launch_bounds__(128)
void ln_kernel(float* __restrict__ x, bf16* __restrict__ xb,
               const float* __restrict__ r,
               const float* __restrict__ g, const float* __restrict__ b)
{
    __shared__ float red[128];
    const long long row = blockIdx.x;
    const int tid = threadIdx.x;
    float* px = x + row * (long long)D_;
    bf16* pb  = xb + row * (long long)D_;
    const float* pr = r + row * (long long)D_;

    float v[4];
    float s = 0.f;
#pragma unroll
    for (int i = 0; i < 4; i++) {
        v[i] = px[tid + i * 128] + pr[tid + i * 128];
        s += v[i];
    }
    red[tid] = s; __syncthreads();
    for (int o = 64; o > 0; o >>= 1) {
        if (tid < o) red[tid] += red[tid + o];
        __syncthreads();
    }
    const float mu = red[0] * (1.f / D_); __syncthreads();

    float sq = 0.f;
#pragma unroll
    for (int i = 0; i < 4; i++) { float d = v[i] - mu; sq += d * d; }
    red[tid] = sq; __syncthreads();
    for (int o = 64; o > 0; o >>= 1) {
        if (tid < o) red[tid] += red[tid + o];
        __syncthreads();
    }
    const float rstd = rsqrtf(red[0] * (1.f / D_) + 1e-5f);
#pragma unroll
    for (int i = 0; i < 4; i++) {
        int c = tid + i * 128;
        float y = (v[i] - mu) * rstd * g[c] + b[c];
        px[c] = y;
        pb[c] = __float2bfloat16(y);
    }
}

// ---------------- mean-pool over S then dot with clf_w ----------------
__global__ __launch_bounds__(256)
void pool_kernel(const float* __restrict__ x, const float* __restrict__ w,
                 const float* __restrict__ cb, float* __restrict__ out)
{
    __shared__ float red[256];
    const int b = blockIdx.x;
    const int tid = threadIdx.x;
    const float* p = x + (long long)b * S_ * D_;
    float acc = 0.f;
    for (int i = tid; i < S_ * D_; i += 256)
        acc += p[i] * w[i & (D_ - 1)];
    red[tid] = acc; __syncthreads();
    for (int o = 128; o > 0; o >>= 1) {
        if (tid < o) red[tid] += red[tid + o];
        __syncthreads();
    }
    if (tid == 0) out[b] = red[0] * (1.f / (float)S_) + cb[0];
}

// ---------------- host orchestration ----------------
extern "C" void kernel_launch(void* const* d_in, const int* in_sizes, int n_in,
                              void* d_out, int out_size)
{
    (void)in_sizes; (void)n_in; (void)out_size;
    const int*   tokens = (const int*)  d_in[0];
    const float* emb    = (const float*)d_in[1];
    const float* Wq     = (const float*)d_in[2];
    const float* bq     = (const float*)d_in[3];
    const float* Wk     = (const float*)d_in[4];
    const float* bk     = (const float*)d_in[5];
    const float* Wv     = (const float*)d_in[6];
    const float* bv     = (const float*)d_in[7];
    const float* Wo     = (const float*)d_in[8];
    const float* bo     = (const float*)d_in[9];
    const float* W1     = (const float*)d_in[10];
    const float* b1     = (const float*)d_in[11];
    const float* W2     = (const float*)d_in[12];
    const float* b2     = (const float*)d_in[13];
    const float* ln1g   = (const float*)d_in[14];
    const float* ln1b   = (const float*)d_in[15];
    const float* ln2g   = (const float*)d_in[16];
    const float* ln2b   = (const float*)d_in[17];
    const float* clfw   = (const float*)d_in[18];
    const float* clfb   = (const float*)d_in[19];
    float* out = (float*)d_out;

    float *x, *r, *sc;
    bf16 *xb, *qb, *kb, *vb, *tb, *hb, *pb;
    bf16 *wqb, *wkb, *wvb, *wob, *w1b, *w2b;
    cudaGetSymbolAddress((void**)&x,   g_x);
    cudaGetSymbolAddress((void**)&r,   g_r);
    cudaGetSymbolAddress((void**)&sc,  g_sc);
    cudaGetSymbolAddress((void**)&xb,  g_xb);
    cudaGetSymbolAddress((void**)&qb,  g_qb);
    cudaGetSymbolAddress((void**)&kb,  g_kb);
    cudaGetSymbolAddress((void**)&vb,  g_vb);
    cudaGetSymbolAddress((void**)&tb,  g_tb);
    cudaGetSymbolAddress((void**)&hb,  g_hb);
    cudaGetSymbolAddress((void**)&pb,  g_pb);
    cudaGetSymbolAddress((void**)&wqb, g_wqb);
    cudaGetSymbolAddress((void**)&wkb, g_wkb);
    cudaGetSymbolAddress((void**)&wvb, g_wvb);
    cudaGetSymbolAddress((void**)&wob, g_wob);
    cudaGetSymbolAddress((void**)&w1b, g_w1b);
    cudaGetSymbolAddress((void**)&w2b, g_w2b);

    // allow 144KB dynamic smem on the GEMM instantiations (idempotent)
    cudaFuncSetAttribute(gemm_bf<0,1>, cudaFuncAttributeMaxDynamicSharedMemorySize, SMEM_BYTES);
    cudaFuncSetAttribute(gemm_bf<0,0>, cudaFuncAttributeMaxDynamicSharedMemorySize, SMEM_BYTES);
    cudaFuncSetAttribute(gemm_bf<1,0>, cudaFuncAttributeMaxDynamicSharedMemorySize, SMEM_BYTES);

    // weight conversion (idempotent per launch)
    cvt_bf<<<(L_ * D_ * D_) / 256, 256>>>(Wq, wqb);
    cvt_bf<<<(L_ * D_ * D_) / 256, 256>>>(Wk, wkb);
    cvt_bf<<<(L_ * D_ * D_) / 256, 256>>>(Wv, wvb);
    cvt_bf<<<(L_ * D_ * D_) / 256, 256>>>(Wo, wob);
    cvt_bf<<<(L_ * D_ * F_) / 256, 256>>>(W1, w1b);
    cvt_bf<<<(L_ * D_ * F_) / 256, 256>>>(W2, w2b);

    embed_kernel<<<(BS_ * D_) / 256, 256>>>(tokens, emb, x, xb);

    const dim3 gProj(D_ / BN, BS_ / BM, 1);      // 2 x 128
    const dim3 gScores(S_ / BN, S_ / BM, B_);    // 8 x 16 x 8
    const dim3 gAV(D_ / BN, S_ / BM, B_);        // 2 x 16 x 8
    const dim3 gF1(F_ / BN, BS_ / BM, 1);        // 8 x 128
    const float kscale = 0.044194173824159216f;  // 1/sqrt(512)

    for (int l = 0; l < L_; l++) {
        const bf16* Wq_l = wqb + (size_t)l * D_ * D_;
        const bf16* Wk_l = wkb + (size_t)l * D_ * D_;
        const bf16* Wv_l = wvb + (size_t)l * D_ * D_;
        const bf16* Wo_l = wob + (size_t)l * D_ * D_;
        const bf16* W1_l = w1b + (size_t)l * D_ * F_;
        const bf16* W2_l = w2b + (size_t)l * F_ * D_;
        const float* bq_l = bq + (size_t)l * D_;
        const float* bk_l = bk + (size_t)l * D_;
        const float* bv_l = bv + (size_t)l * D_;
        const float* bo_l = bo + (size_t)l * D_;
        const float* b1_l = b1 + (size_t)l * F_;
        const float* b2_l = b2 + (size_t)l * D_;

        gemm_bf<0, 1><<<gProj, 256, SMEM_BYTES>>>(xb, Wq_l, bq_l, qb, BS_, D_, D_, 0, 0, 0, 1.f, 0);
        gemm_bf<0, 1><<<gProj, 256, SMEM_BYTES>>>(xb, Wk_l, bk_l, kb, BS_, D_, D_, 0, 0, 0, 1.f, 0);
        gemm_bf<0, 1><<<gProj, 256, SMEM_BYTES>>>(xb, Wv_l, bv_l, vb, BS_, D_, D_, 0, 0, 0, 1.f, 0);

        // scores[b] = q_b @ k_b^T (f32 out; scale applied in softmax)
        gemm_bf<1, 0><<<gScores, 256, SMEM_BYTES>>>(qb, kb, nullptr, sc, S_, S_, D_,
                                        (long long)S_ * D_, (long long)S_ * D_,
                                        (long long)S_ * S_, 1.f, 0);
        softmax_bf<<<B_ * S_, 256>>>(sc, pb, kscale);

        // t[b] = attn_b @ v_b   (bf16 out)
        gemm_bf<0, 1><<<gAV, 256, SMEM_BYTES>>>(pb, vb, nullptr, tb, S_, D_, S_,
                                    (long long)S_ * S_, (long long)S_ * D_,
                                    (long long)S_ * D_, 1.f, 0);

        // attn_out = t @ Wo + bo  (f32 out for residual)
        gemm_bf<0, 0><<<gProj, 256, SMEM_BYTES>>>(tb, Wo_l, bo_l, r, BS_, D_, D_, 0, 0, 0, 1.f, 0);
        ln_kernel<<<BS_, 128>>>(x, xb, r, ln1g + (size_t)l * D_, ln1b + (size_t)l * D_);

        // FFN
        gemm_bf<0, 1><<<gF1, 256, SMEM_BYTES>>>(xb, W1_l, b1_l, hb, BS_, F_, D_, 0, 0, 0, 1.f, 1);
        gemm_bf<0, 0><<<gProj, 256, SMEM_BYTES>>>(hb, W2_l, b2_l, r, BS_, D_, F_, 0, 0, 0, 1.f, 0);
        ln_kernel<<<BS_, 128>>>(x, xb, r, ln2g + (size_t)l * D_, ln2b + (size_t)l * D_);
    }

    pool_kernel<<<B_, 256>>>(x, clfw, clfb, out);
}

// round 14
// speedup vs baseline: 6.7103x; 1.0089x over previous
#include <cuda_runtime.h>
#include <cuda_bf16.h>
#include <cstdint>

typedef __nv_bfloat16 bf16;

#define D_  512
#define B_  8
#define S_  2048
#define F_  2048
#define L_  4
#define BS_ (B_*S_)
#define D3_ (3*D_)

// ---------------- scratch (static device globals; no allocation) ----------------
__device__ __align__(256) float g_x [BS_*D_];            // f32 master activations
__device__ __align__(256) float g_r [BS_*D_];            // f32 residual branch
__device__ __align__(256) float g_sc[(size_t)B_*S_*S_];  // f32 attention scores
__device__ __align__(256) bf16  g_xb[BS_*D_];            // bf16 operand copies
__device__ __align__(256) bf16  g_qkv[(size_t)BS_*D3_];  // fused QKV output [BS,1536]
__device__ __align__(256) bf16  g_tb[BS_*D_];
__device__ __align__(256) bf16  g_hb[(size_t)BS_*F_];
__device__ __align__(256) bf16  g_pb[(size_t)B_*S_*S_];  // bf16 softmax probs
__device__ __align__(256) bf16  g_wqkv[(size_t)L_*D_*D3_]; // [L][512][1536] concat W{q,k,v}
__device__ __align__(256) float g_bqkv[L_*D3_];            // [L][1536] concat b{q,k,v}
__device__ __align__(256) bf16  g_wob[L_*D_*D_];
__device__ __align__(256) bf16  g_w1b[(size_t)L_*D_*F_];
__device__ __align__(256) bf16  g_w2b[(size_t)L_*D_*F_];

// ---------------- weight converts ----------------
__global__ void cvt_bf(const float* __restrict__ s, bf16* __restrict__ d)
{
    int i = blockIdx.x * 256 + threadIdx.x;
    d[i] = __float2bfloat16(s[i]);
}
// concat Wq/Wk/Wv: [L][512][512] each -> [L][512][1536]
__global__ void cvt_qkv_w(const float* __restrict__ wq, const float* __restrict__ wk,
                          const float* __restrict__ wv, bf16* __restrict__ d)
{
    int i = blockIdx.x * 256 + threadIdx.x;      // over L*D*D
    int l = i / (D_ * D_), rem = i % (D_ * D_);
    int k = rem / D_, n = rem % D_;
    size_t o = (size_t)l * D_ * D3_ + (size_t)k * D3_ + n;
    d[o]           = __float2bfloat16(wq[i]);
    d[o + D_]      = __float2bfloat16(wk[i]);
    d[o + 2 * D_]  = __float2bfloat16(wv[i]);
}
__global__ void cvt_qkv_b(const float* __restrict__ bq, const float* __restrict__ bk,
                          const float* __restrict__ bv, float* __restrict__ d)
{
    int i = blockIdx.x * 256 + threadIdx.x;      // over L*D
    int l = i / D_, n = i % D_;
    d[l * D3_ + n]          = bq[i];
    d[l * D3_ + D_ + n]     = bk[i];
    d[l * D3_ + 2 * D_ + n] = bv[i];
}

// ---------------- embedding + sinusoidal PE (f32 + bf16 out) ----------------
__global__ void embed_kernel(const int* __restrict__ tok,
                             const float* __restrict__ emb,
                             float* __restrict__ x, bf16* __restrict__ xb)
{
    int idx = blockIdx.x * blockDim.x + threadIdx.x;
    int d  = idx & (D_ - 1);
    int bs = idx >> 9;
    int s  = bs & (S_ - 1);
    int t  = tok[bs];
    float dv  = expf(-(float)(d & ~1) * (9.210340371976184f / (float)D_));
    float arg = (float)s * dv;
    float pe  = (d & 1) ? cosf(arg) : sinf(arg);
    float v = emb[(size_t)t * D_ + d] + pe;
    x[idx]  = v;
    xb[idx] = __float2bfloat16(v);
}

// ---------------- bf16 tensor-core GEMM (128x256x64, 4-stage cp.async) ----------------
// C = scale*(A @ op(B)) [+bias] [relu]
// A: [M,K] bf16, row stride ldA. NT=0: B [K,N] row stride ldB. NT=1: B [N,K] row stride ldB.
// OUTB=1: C bf16; OUTB=0: C f32. C row stride ldC.
// 256 threads = 8 warps (2 M x 4 N), warp tile 64x64, m16n8k16 MMA, ldmatrix,
// XOR-swizzled smem, 4-stage cp.async pipeline, one __syncthreads per k-tile.

#define BM 128
#define BN 256
#define BK 64
#define STAGES 4
#define A_STAGE_BYTES (BM * 128)                  // 16384
#define B_STAGE_BYTES 32768                       // NT: 256 rows x 128B; NN: 64 rows x 512B
#define STG_BYTES (A_STAGE_BYTES + B_STAGE_BYTES) // 49152
#define SMEM_BYTES (STAGES * STG_BYTES)           // 196608

__device__ __forceinline__ void cp16(uint32_t dst, const void* src) {
    asm volatile("cp.async.cg.shared.global [%0], [%1], 16;" :: "r"(dst), "l"(src));
}
__device__ __forceinline__ void ldsm4(uint32_t* r, uint32_t addr) {
    asm volatile("ldmatrix.sync.aligned.m8n8.x4.shared.b16 {%0,%1,%2,%3}, [%4];"
        : "=r"(r[0]), "=r"(r[1]), "=r"(r[2]), "=r"(r[3]) : "r"(addr));
}
__device__ __forceinline__ void ldsm4t(uint32_t* r, uint32_t addr) {
    asm volatile("ldmatrix.sync.aligned.m8n8.x4.trans.shared.b16 {%0,%1,%2,%3}, [%4];"
        : "=r"(r[0]), "=r"(r[1]), "=r"(r[2]), "=r"(r[3]) : "r"(addr));
}
__device__ __forceinline__ void mma16(float* c, const uint32_t* a, const uint32_t* b) {
    asm volatile(
        "mma.sync.aligned.m16n8k16.row.col.f32.bf16.bf16.f32 "
        "{%0,%1,%2,%3},{%4,%5,%6,%7},{%8,%9},{%0,%1,%2,%3};"
        : "+f"(c[0]), "+f"(c[1]), "+f"(c[2]), "+f"(c[3])
        : "r"(a[0]), "r"(a[1]), "r"(a[2]), "r"(a[3]), "r"(b[0]), "r"(b[1]));
}

template<int NT, int OUTB>
__global__ __launch_bounds__(256, 1)
void gemm_bf(const bf16* __restrict__ A, const bf16* __restrict__ B,
             const float* __restrict__ bias, void* __restrict__ Cv,
             int K, int ldA, int ldB, int ldC,
             long long sA, long long sB, long long sC,
             float scale, int relu)
{
    extern __shared__ __align__(128) char smem[];

    const int tid  = threadIdx.x;
    const int lane = tid & 31;
    const int wid  = tid >> 5;
    const int wm   = wid >> 2;          // 0..1 (M dir, 64 rows each)
    const int wn   = wid & 3;           // 0..3 (N dir, 64 cols each)
    const int l7   = lane & 7;

    const int bx = blockIdx.x, by = blockIdx.y, bz = blockIdx.z;

    A += (long long)bz * sA + (long long)by * BM * ldA;
    long long cbase = (long long)bz * sC + (long long)by * BM * ldC + (long long)bx * BN;
    if (NT) B += (long long)bz * sB + (long long)bx * BN * ldB;
    else    B += (long long)bz * sB + bx * BN;

    const uint32_t sA0 = (uint32_t)__cvta_generic_to_shared(smem);
    const uint32_t sB0 = sA0 + STAGES * A_STAGE_BYTES;

    float acc[4][8][4];
#pragma unroll
    for (int i = 0; i < 4; i++)
#pragma unroll
        for (int j = 0; j < 8; j++)
#pragma unroll
            for (int r = 0; r < 4; r++) acc[i][j][r] = 0.f;

    // ---- fragment address precompute (verified R12 scheme) ----
    const int rowA0 = wm * 64 + ((lane >> 3) & 1) * 8 + l7;   // rowA0 & 7 == l7
    const int khA   = (lane >> 4) & 1;
    const int rowB0 = wn * 64 + ((lane >> 4) & 1) * 8 + l7;   // NT; rowB0 & 7 == l7
    const int khB   = (lane >> 3) & 1;
    const int krow0 = ((lane >> 3) & 1) * 8 + l7;             // NN (trans)
    const int nu0   = wn * 8 + ((lane >> 4) & 1);             // 16B n-unit within 512B row

    const int kt = K / BK;

    auto load_tile = [&](int stg, int k0) {
        uint32_t aS = sA0 + stg * A_STAGE_BYTES;
#pragma unroll
        for (int i = 0; i < 4; i++) {
            int idx = tid + i * 256;                 // 0..1023
            int r = idx >> 3, u = idx & 7;
            cp16(aS + r * 128 + (uint32_t)((u ^ (r & 7)) << 4),
                 A + (long long)r * ldA + k0 + u * 8);
        }
        uint32_t bS = sB0 + stg * B_STAGE_BYTES;
        if (NT) {
#pragma unroll
            for (int i = 0; i < 8; i++) {
                int idx = tid + i * 256;             // 0..2047
                int n = idx >> 3, u = idx & 7;
                cp16(bS + n * 128 + (uint32_t)((u ^ (n & 7)) << 4),
                     B + (long long)n * ldB + k0 + u * 8);
            }
        } else {
#pragma unroll
            for (int i = 0; i < 8; i++) {
                int idx = tid + i * 256;             // 0..2047
                int k = idx >> 5, u = idx & 31;
                cp16(bS + k * 512 + (uint32_t)((u ^ (k & 7)) << 4),
                     B + (long long)(k0 + k) * ldB + u * 8);
            }
        }
        asm volatile("cp.async.commit_group;");
    };

    // prologue: fill stages 0..2
    load_tile(0, 0);
    load_tile(1, BK);
    load_tile(2, 2 * BK);

    for (int t = 0; t < kt; t++) {
        int rem = kt - 1 - t;
        if (rem >= 2)      asm volatile("cp.async.wait_group 2;");
        else if (rem == 1) asm volatile("cp.async.wait_group 1;");
        else               asm volatile("cp.async.wait_group 0;");
        __syncthreads();   // all threads done with stage (t+3)&3's previous contents

        if (t + 3 < kt) load_tile((t + 3) & 3, (t + 3) * BK);

        const int stg = t & 3;
        const uint32_t aS = sA0 + stg * A_STAGE_BYTES;
        const uint32_t bS = sB0 + stg * B_STAGE_BYTES;
        const uint32_t aFrag = aS + rowA0 * 128;
        const uint32_t bFragNT = bS + rowB0 * 128;

#pragma unroll
        for (int ks = 0; ks < 4; ks++) {
            uint32_t a[4][4], b[8][2];
            const uint32_t auoff = (uint32_t)(((2 * ks + khA) ^ l7) << 4);
#pragma unroll
            for (int i = 0; i < 4; i++)
                ldsm4(a[i], aFrag + i * 2048 + auoff);
            if (NT) {
                const uint32_t buoff = (uint32_t)(((2 * ks + khB) ^ l7) << 4);
#pragma unroll
                for (int jb = 0; jb < 4; jb++) {
                    uint32_t t0[4];
                    ldsm4(t0, bFragNT + jb * 2048 + buoff);
                    b[2 * jb][0] = t0[0]; b[2 * jb][1] = t0[1];
                    b[2 * jb + 1][0] = t0[2]; b[2 * jb + 1][1] = t0[3];
                }
            } else {
                uint32_t kb = bS + (ks * 16 + krow0) * 512;
#pragma unroll
                for (int jb = 0; jb < 4; jb++) {
                    uint32_t t0[4];
                    ldsm4t(t0, kb + (uint32_t)(((nu0 + 2 * jb) ^ l7) << 4));
                    b[2 * jb][0] = t0[0]; b[2 * jb][1] = t0[1];
                    b[2 * jb + 1][0] = t0[2]; b[2 * jb + 1][1] = t0[3];
                }
            }
#pragma unroll
            for (int i = 0; i < 4; i++)
#pragma unroll
                for (int j = 0; j < 8; j++)
                    mma16(acc[i][j], a[i], b[j]);
        }
    }

    // ---- epilogue ----
    const int gr = lane >> 2, tg = lane & 3;
#pragma unroll
    for (int i = 0; i < 4; i++) {
        int r0 = wm * 64 + i * 16 + gr;
#pragma unroll
        for (int j = 0; j < 8; j++) {
            int col = wn * 64 + j * 8 + 2 * tg;
            float b0 = 0.f, b1 = 0.f;
            if (bias) {
                b0 = bias[bx * BN + col];
                b1 = bias[bx * BN + col + 1];
            }
            float v0 = acc[i][j][0] * scale + b0;
            float v1 = acc[i][j][1] * scale + b1;
            float v2 = acc[i][j][2] * scale + b0;
            float v3 = acc[i][j][3] * scale + b1;
            if (relu) {
                v0 = fmaxf(v0, 0.f); v1 = fmaxf(v1, 0.f);
                v2 = fmaxf(v2, 0.f); v3 = fmaxf(v3, 0.f);
            }
            if (OUTB) {
                bf16* C = (bf16*)Cv;
                __nv_bfloat162 p0, p1;
                p0.x = __float2bfloat16(v0); p0.y = __float2bfloat16(v1);
                p1.x = __float2bfloat16(v2); p1.y = __float2bfloat16(v3);
                *(__nv_bfloat162*)(C + cbase + (long long)r0 * ldC + col)       = p0;
                *(__nv_bfloat162*)(C + cbase + (long long)(r0 + 8) * ldC + col) = p1;
            } else {
                float* C = (float*)Cv;
                *(float2*)(C + cbase + (long long)r0 * ldC + col)       = make_float2(v0, v1);
                *(float2*)(C + cbase + (long long)(r0 + 8) * ldC + col) = make_float2(v2, v3);
            }
        }
    }
}

// ---------------- row softmax: f32 in, bf16 out, with pre-scale ----------------
__global__ __launch_bounds__(256)
void softmax_bf(const float* __restrict__ sc, bf16* __restrict__ pb, float scale)
{
    __shared__ float red[256];
    const long long row = blockIdx.x;
    const float* p = sc + row * (long long)S_;
    bf16* o = pb + row * (long long)S_;
    const int tid = threadIdx.x;

    float v[8];
    float m = -1e30f;
#pragma unroll
    for (int i = 0; i < 8; i++) {
        v[i] = p[tid + i * 256] * scale;
        m = fmaxf(m, v[i]);
    }
    red[tid] = m; __syncthreads();
    for (int o2 = 128; o2 > 0; o2 >>= 1) {
        if (tid < o2) red[tid] = fmaxf(red[tid], red[tid + o2]);
        __syncthreads();
    }
    m = red[0]; __syncthreads();

    float s = 0.f;
#pragma unroll
    for (int i = 0; i < 8; i++) { v[i] = expf(v[i] - m); s += v[i]; }
    red[tid] = s; __syncthreads();
    for (int o2 = 128; o2 > 0; o2 >>= 1) {
        if (tid < o2) red[tid] += red[tid + o2];
        __syncthreads();
    }
    float inv = 1.f / red[0];
#pragma unroll
    for (int i = 0; i < 8; i++)
        o[tid + i * 256] = __float2bfloat16(v[i] * inv);
}

// ---------------- residual + layernorm: x = LN(x + r), writes f32 + bf16 ----------------
__global__ __launch_bounds__(128)
void ln_kernel(float* __restrict__ x, bf16* __restrict__ xb,
               const float* __restrict__ r,
               const float* __restrict__ g, const float* __restrict__ b)
{
    __shared__ float red[128];
    const long long row = blockIdx.x;
    const int tid = threadIdx.x;
    float* px = x + row * (long long)D_;
    bf16* pb  = xb + row * (long long)D_;
    const float* pr = r + row * (long long)D_;

    float v[4];
    float s = 0.f;
#pragma unroll
    for (int i = 0; i < 4; i++) {
        v[i] = px[tid + i * 128] + pr[tid + i * 128];
        s += v[i];
    }
    red[tid] = s; __syncthreads();
    for (int o = 64; o > 0; o >>= 1) {
        if (tid < o) red[tid] += red[tid + o];
        __syncthreads();
    }
    const float mu = red[0] * (1.f / D_); __syncthreads();

    float sq = 0.f;
#pragma unroll
    for (int i = 0; i < 4; i++) { float d = v[i] - mu; sq += d * d; }
    red[tid] = sq; __syncthreads();
    for (int o = 64; o > 0; o >>= 1) {
        if (tid < o) red[tid] += red[tid + o];
        __syncthreads();
    }
    const float rstd = rsqrtf(red[0] * (1.f / D_) + 1e-5f);
#pragma unroll
    for (int i = 0; i < 4; i++) {
        int c = tid + i * 128;
        float y = (v[i] - mu) * rstd * g[c] + b[c];
        px[c] = y;
        pb[c] = __float2bfloat16(y);
    }
}

// ---------------- mean-pool over S then dot with clf_w ----------------
__global__ __launch_bounds__(256)
void pool_kernel(const float* __restrict__ x, const float* __restrict__ w,
                 const float* __restrict__ cb, float* __restrict__ out)
{
    __shared__ float red[256];
    const int b = blockIdx.x;
    const int tid = threadIdx.x;
    const float* p = x + (long long)b * S_ * D_;
    float acc = 0.f;
    for (int i = tid; i < S_ * D_; i += 256)
        acc += p[i] * w[i & (D_ - 1)];
    red[tid] = acc; __syncthreads();
    for (int o = 128; o > 0; o >>= 1) {
        if (tid < o) red[tid] += red[tid + o];
        __syncthreads();
    }
    if (tid == 0) out[b] = red[0] * (1.f / (float)S_) + cb[0];
}

// ---------------- host orchestration ----------------
extern "C" void kernel_launch(void* const* d_in, const int* in_sizes, int n_in,
                              void* d_out, int out_size)
{
    (void)in_sizes; (void)n_in; (void)out_size;
    const int*   tokens = (const int*)  d_in[0];
    const float* emb    = (const float*)d_in[1];
    const float* Wq     = (const float*)d_in[2];
    const float* bq     = (const float*)d_in[3];
    const float* Wk     = (const float*)d_in[4];
    const float* bk     = (const float*)d_in[5];
    const float* Wv     = (const float*)d_in[6];
    const float* bv     = (const float*)d_in[7];
    const float* Wo     = (const float*)d_in[8];
    const float* bo     = (const float*)d_in[9];
    const float* W1     = (const float*)d_in[10];
    const float* b1     = (const float*)d_in[11];
    const float* W2     = (const float*)d_in[12];
    const float* b2     = (const float*)d_in[13];
    const float* ln1g   = (const float*)d_in[14];
    const float* ln1b   = (const float*)d_in[15];
    const float* ln2g   = (const float*)d_in[16];
    const float* ln2b   = (const float*)d_in[17];
    const float* clfw   = (const float*)d_in[18];
    const float* clfb   = (const float*)d_in[19];
    float* out = (float*)d_out;

    float *x, *r, *sc, *bqkv;
    bf16 *xb, *qkv, *tb, *hb, *pb;
    bf16 *wqkv, *wob, *w1b, *w2b;
    cudaGetSymbolAddress((void**)&x,    g_x);
    cudaGetSymbolAddress((void**)&r,    g_r);
    cudaGetSymbolAddress((void**)&sc,   g_sc);
    cudaGetSymbolAddress((void**)&xb,   g_xb);
    cudaGetSymbolAddress((void**)&qkv,  g_qkv);
    cudaGetSymbolAddress((void**)&tb,   g_tb);
    cudaGetSymbolAddress((void**)&hb,   g_hb);
    cudaGetSymbolAddress((void**)&pb,   g_pb);
    cudaGetSymbolAddress((void**)&wqkv, g_wqkv);
    cudaGetSymbolAddress((void**)&bqkv, g_bqkv);
    cudaGetSymbolAddress((void**)&wob,  g_wob);
    cudaGetSymbolAddress((void**)&w1b,  g_w1b);
    cudaGetSymbolAddress((void**)&w2b,  g_w2b);

    cudaFuncSetAttribute(gemm_bf<0,1>, cudaFuncAttributeMaxDynamicSharedMemorySize, SMEM_BYTES);
    cudaFuncSetAttribute(gemm_bf<0,0>, cudaFuncAttributeMaxDynamicSharedMemorySize, SMEM_BYTES);
    cudaFuncSetAttribute(gemm_bf<1,0>, cudaFuncAttributeMaxDynamicSharedMemorySize, SMEM_BYTES);

    // weight conversion / concatenation (idempotent per launch)
    cvt_qkv_w<<<(L_ * D_ * D_) / 256, 256>>>(Wq, Wk, Wv, wqkv);
    cvt_qkv_b<<<(L_ * D_) / 256, 256>>>(bq, bk, bv, bqkv);
    cvt_bf<<<(L_ * D_ * D_) / 256, 256>>>(Wo, wob);
    cvt_bf<<<(L_ * D_ * F_) / 256, 256>>>(W1, w1b);
    cvt_bf<<<(L_ * D_ * F_) / 256, 256>>>(W2, w2b);

    embed_kernel<<<(BS_ * D_) / 256, 256>>>(tokens, emb, x, xb);

    const dim3 gQKV(D3_ / BN, BS_ / BM, 1);      // 6 x 128 = 768 CTAs
    const dim3 gProj(D_ / BN, BS_ / BM, 1);      // 2 x 128
    const dim3 gScores(S_ / BN, S_ / BM, B_);    // 8 x 16 x 8
    const dim3 gAV(D_ / BN, S_ / BM, B_);        // 2 x 16 x 8
    const dim3 gF1(F_ / BN, BS_ / BM, 1);        // 8 x 128
    const float kscale = 0.044194173824159216f;  // 1/sqrt(512)

    for (int l = 0; l < L_; l++) {
        const bf16* Wqkv_l = wqkv + (size_t)l * D_ * D3_;
        const float* bqkv_l = bqkv + (size_t)l * D3_;
        const bf16* Wo_l = wob + (size_t)l * D_ * D_;
        const bf16* W1_l = w1b + (size_t)l * D_ * F_;
        const bf16* W2_l = w2b + (size_t)l * F_ * D_;
        const float* bo_l = bo + (size_t)l * D_;
        const float* b1_l = b1 + (size_t)l * F_;
        const float* b2_l = b2 + (size_t)l * D_;

        // fused QKV: qkv[BS,1536] = xb @ Wqkv + bqkv
        gemm_bf<0, 1><<<gQKV, 256, SMEM_BYTES>>>(xb, Wqkv_l, bqkv_l, qkv,
                                                 D_, D_, D3_, D3_, 0, 0, 0, 1.f, 0);

        // scores[b] = Q_b @ K_b^T (f32; scale applied in softmax)
        gemm_bf<1, 0><<<gScores, 256, SMEM_BYTES>>>(qkv, qkv + D_, nullptr, sc,
                                                    D_, D3_, D3_, S_,
                                                    (long long)S_ * D3_, (long long)S_ * D3_,
                                                    (long long)S_ * S_, 1.f, 0);
        softmax_bf<<<B_ * S_, 256>>>(sc, pb, kscale);

        // t[b] = P_b @ V_b (bf16 out)
        gemm_bf<0, 1><<<gAV, 256, SMEM_BYTES>>>(pb, qkv + 2 * D_, nullptr, tb,
                                                S_, S_, D3_, D_,
                                                (long long)S_ * S_, (long long)S_ * D3_,
                                                (long long)S_ * D_, 1.f, 0);

        // attn_out = t @ Wo + bo (f32 out for residual)
        gemm_bf<0, 0><<<gProj, 256, SMEM_BYTES>>>(tb, Wo_l, bo_l, r,
                                                  D_, D_, D_, D_, 0, 0, 0, 1.f, 0);
        ln_kernel<<<BS_, 128>>>(x, xb, r, ln1g + (size_t)l * D_, ln1b + (size_t)l * D_);

        // FFN
        gemm_bf<0, 1><<<gF1, 256, SMEM_BYTES>>>(xb, W1_l, b1_l, hb,
                                                D_, D_, F_, F_, 0, 0, 0, 1.f, 1);
        gemm_bf<0, 0><<<gProj, 256, SMEM_BYTES>>>(hb, W2_l, b2_l, r,
                                                  F_, F_, D_, D_, 0, 0, 0, 1.f, 0);
        ln_kernel<<<BS_, 128>>>(x, xb, r, ln2g + (size_t)l * D_, ln2b + (size_t)l * D_);
    }

    pool_kernel<<<B_, 256>>>(x, clfw, clfb, out);
}

// round 16
// speedup vs baseline: 6.8476x; 1.0205x over previous
#include <cuda_runtime.h>
#include <cuda_bf16.h>
#include <cstdint>

typedef __nv_bfloat16 bf16;

#define D_  512
#define B_  8
#define S_  2048
#define F_  2048
#define L_  4
#define BS_ (B_*S_)
#define D3_ (3*D_)

// ---------------- scratch (static device globals; no allocation) ----------------
__device__ __align__(256) float g_x [BS_*D_];            // f32 master activations
__device__ __align__(256) float g_r [BS_*D_];            // f32 residual-sum branch
__device__ __align__(256) float g_sc[(size_t)B_*S_*S_];  // f32 attention scores
__device__ __align__(256) bf16  g_xb[BS_*D_];            // bf16 operand copies
__device__ __align__(256) bf16  g_qkv[(size_t)BS_*D3_];  // fused QKV output [BS,1536]
__device__ __align__(256) bf16  g_tb[BS_*D_];
__device__ __align__(256) bf16  g_hb[(size_t)BS_*F_];
__device__ __align__(256) bf16  g_pb[(size_t)B_*S_*S_];  // bf16 softmax probs
__device__ __align__(256) bf16  g_wqkv[(size_t)L_*D_*D3_]; // [L][512][1536] concat W{q,k,v}
__device__ __align__(256) float g_bqkv[L_*D3_];            // [L][1536] concat b{q,k,v}
__device__ __align__(256) bf16  g_wob[L_*D_*D_];
__device__ __align__(256) bf16  g_w1b[(size_t)L_*D_*F_];
__device__ __align__(256) bf16  g_w2b[(size_t)L_*D_*F_];

// ---------------- weight converts ----------------
__global__ void cvt_bf(const float* __restrict__ s, bf16* __restrict__ d)
{
    int i = blockIdx.x * 256 + threadIdx.x;
    d[i] = __float2bfloat16(s[i]);
}
// concat Wq/Wk/Wv: [L][512][512] each -> [L][512][1536]
__global__ void cvt_qkv_w(const float* __restrict__ wq, const float* __restrict__ wk,
                          const float* __restrict__ wv, bf16* __restrict__ d)
{
    int i = blockIdx.x * 256 + threadIdx.x;      // over L*D*D
    int l = i / (D_ * D_), rem = i % (D_ * D_);
    int k = rem / D_, n = rem % D_;
    size_t o = (size_t)l * D_ * D3_ + (size_t)k * D3_ + n;
    d[o]           = __float2bfloat16(wq[i]);
    d[o + D_]      = __float2bfloat16(wk[i]);
    d[o + 2 * D_]  = __float2bfloat16(wv[i]);
}
__global__ void cvt_qkv_b(const float* __restrict__ bq, const float* __restrict__ bk,
                          const float* __restrict__ bv, float* __restrict__ d)
{
    int i = blockIdx.x * 256 + threadIdx.x;      // over L*D
    int l = i / D_, n = i % D_;
    d[l * D3_ + n]          = bq[i];
    d[l * D3_ + D_ + n]     = bk[i];
    d[l * D3_ + 2 * D_ + n] = bv[i];
}

// ---------------- embedding + sinusoidal PE (f32 + bf16 out) ----------------
__global__ void embed_kernel(const int* __restrict__ tok,
                             const float* __restrict__ emb,
                             float* __restrict__ x, bf16* __restrict__ xb)
{
    int idx = blockIdx.x * blockDim.x + threadIdx.x;
    int d  = idx & (D_ - 1);
    int bs = idx >> 9;
    int s  = bs & (S_ - 1);
    int t  = tok[bs];
    float dv  = expf(-(float)(d & ~1) * (9.210340371976184f / (float)D_));
    float arg = (float)s * dv;
    float pe  = (d & 1) ? cosf(arg) : sinf(arg);
    float v = emb[(size_t)t * D_ + d] + pe;
    x[idx]  = v;
    xb[idx] = __float2bfloat16(v);
}

// ---------------- bf16 tensor-core GEMM (128x256x64, 4-stage cp.async) ----------------
// C = scale*(A @ op(B)) [+bias] [+resid] [relu]
// A: [M,K] bf16, row stride ldA. NT=0: B [K,N] row stride ldB. NT=1: B [N,K] row stride ldB.
// OUTB=1: C bf16; OUTB=0: C f32 (resid: optional f32 same geometry as C, added in epilogue).
// 256 threads = 8 warps (2 M x 4 N), warp tile 64x64, m16n8k16 MMA, ldmatrix,
// XOR-swizzled smem, 4-stage cp.async pipeline, fragment double-buffering.

#define BM 128
#define BN 256
#define BK 64
#define STAGES 4
#define A_STAGE_BYTES (BM * 128)                  // 16384
#define B_STAGE_BYTES 32768                       // NT: 256 rows x 128B; NN: 64 rows x 512B
#define STG_BYTES (A_STAGE_BYTES + B_STAGE_BYTES) // 49152
#define SMEM_BYTES (STAGES * STG_BYTES)           // 196608

__device__ __forceinline__ void cp16(uint32_t dst, const void* src) {
    asm volatile("cp.async.cg.shared.global [%0], [%1], 16;" :: "r"(dst), "l"(src));
}
__device__ __forceinline__ void ldsm4(uint32_t* r, uint32_t addr) {
    asm volatile("ldmatrix.sync.aligned.m8n8.x4.shared.b16 {%0,%1,%2,%3}, [%4];"
        : "=r"(r[0]), "=r"(r[1]), "=r"(r[2]), "=r"(r[3]) : "r"(addr));
}
__device__ __forceinline__ void ldsm4t(uint32_t* r, uint32_t addr) {
    asm volatile("ldmatrix.sync.aligned.m8n8.x4.trans.shared.b16 {%0,%1,%2,%3}, [%4];"
        : "=r"(r[0]), "=r"(r[1]), "=r"(r[2]), "=r"(r[3]) : "r"(addr));
}
__device__ __forceinline__ void mma16(float* c, const uint32_t* a, const uint32_t* b) {
    asm volatile(
        "mma.sync.aligned.m16n8k16.row.col.f32.bf16.bf16.f32 "
        "{%0,%1,%2,%3},{%4,%5,%6,%7},{%8,%9},{%0,%1,%2,%3};"
        : "+f"(c[0]), "+f"(c[1]), "+f"(c[2]), "+f"(c[3])
        : "r"(a[0]), "r"(a[1]), "r"(a[2]), "r"(a[3]), "r"(b[0]), "r"(b[1]));
}

template<int NT, int OUTB>
__global__ __launch_bounds__(256, 1)
void gemm_bf(const bf16* __restrict__ A, const bf16* __restrict__ B,
             const float* __restrict__ bias, const float* __restrict__ resid,
             void* __restrict__ Cv,
             int K, int ldA, int ldB, int ldC,
             long long sA, long long sB, long long sC,
             float scale, int relu)
{
    extern __shared__ __align__(128) char smem[];

    const int tid  = threadIdx.x;
    const int lane = tid & 31;
    const int wid  = tid >> 5;
    const int wm   = wid >> 2;          // 0..1 (M dir, 64 rows each)
    const int wn   = wid & 3;           // 0..3 (N dir, 64 cols each)
    const int l7   = lane & 7;

    const int bx = blockIdx.x, by = blockIdx.y, bz = blockIdx.z;

    A += (long long)bz * sA + (long long)by * BM * ldA;
    long long cbase = (long long)bz * sC + (long long)by * BM * ldC + (long long)bx * BN;
    if (NT) B += (long long)bz * sB + (long long)bx * BN * ldB;
    else    B += (long long)bz * sB + bx * BN;

    const uint32_t sA0 = (uint32_t)__cvta_generic_to_shared(smem);
    const uint32_t sB0 = sA0 + STAGES * A_STAGE_BYTES;

    float acc[4][8][4];
#pragma unroll
    for (int i = 0; i < 4; i++)
#pragma unroll
        for (int j = 0; j < 8; j++)
#pragma unroll
            for (int r = 0; r < 4; r++) acc[i][j][r] = 0.f;

    // ---- fragment address precompute (verified R12 scheme) ----
    const int rowA0 = wm * 64 + ((lane >> 3) & 1) * 8 + l7;   // rowA0 & 7 == l7
    const int khA   = (lane >> 4) & 1;
    const int rowB0 = wn * 64 + ((lane >> 4) & 1) * 8 + l7;   // NT; rowB0 & 7 == l7
    const int khB   = (lane >> 3) & 1;
    const int krow0 = ((lane >> 3) & 1) * 8 + l7;             // NN (trans)
    const int nu0   = wn * 8 + ((lane >> 4) & 1);             // 16B n-unit within 512B row

    const int kt = K / BK;

    auto load_tile = [&](int stg, int k0) {
        uint32_t aS = sA0 + stg * A_STAGE_BYTES;
#pragma unroll
        for (int i = 0; i < 4; i++) {
            int idx = tid + i * 256;                 // 0..1023
            int r = idx >> 3, u = idx & 7;
            cp16(aS + r * 128 + (uint32_t)((u ^ (r & 7)) << 4),
                 A + (long long)r * ldA + k0 + u * 8);
        }
        uint32_t bS = sB0 + stg * B_STAGE_BYTES;
        if (NT) {
#pragma unroll
            for (int i = 0; i < 8; i++) {
                int idx = tid + i * 256;             // 0..2047
                int n = idx >> 3, u = idx & 7;
                cp16(bS + n * 128 + (uint32_t)((u ^ (n & 7)) << 4),
                     B + (long long)n * ldB + k0 + u * 8);
            }
        } else {
#pragma unroll
            for (int i = 0; i < 8; i++) {
                int idx = tid + i * 256;             // 0..2047
                int k = idx >> 5, u = idx & 31;
                cp16(bS + k * 512 + (uint32_t)((u ^ (k & 7)) << 4),
                     B + (long long)(k0 + k) * ldB + u * 8);
            }
        }
        asm volatile("cp.async.commit_group;");
    };

    // prologue: fill stages 0..2
    load_tile(0, 0);
    load_tile(1, BK);
    load_tile(2, 2 * BK);

    for (int t = 0; t < kt; t++) {
        int rem = kt - 1 - t;
        if (rem >= 2)      asm volatile("cp.async.wait_group 2;");
        else if (rem == 1) asm volatile("cp.async.wait_group 1;");
        else               asm volatile("cp.async.wait_group 0;");
        __syncthreads();   // all threads done with stage (t+3)&3's previous contents

        if (t + 3 < kt) load_tile((t + 3) & 3, (t + 3) * BK);

        const int stg = t & 3;
        const uint32_t aS = sA0 + stg * A_STAGE_BYTES;
        const uint32_t bS = sB0 + stg * B_STAGE_BYTES;
        const uint32_t aFrag = aS + rowA0 * 128;
        const uint32_t bFragNT = bS + rowB0 * 128;

        // fragment double-buffer: prefetch ks+1's ldmatrix before ks's MMAs
        uint32_t a[2][4][4], b[2][8][2];

        auto load_frag = [&](int ks, int fb) {
            const uint32_t auoff = (uint32_t)(((2 * ks + khA) ^ l7) << 4);
#pragma unroll
            for (int i = 0; i < 4; i++)
                ldsm4(a[fb][i], aFrag + i * 2048 + auoff);
            if (NT) {
                const uint32_t buoff = (uint32_t)(((2 * ks + khB) ^ l7) << 4);
#pragma unroll
                for (int jb = 0; jb < 4; jb++) {
                    uint32_t t0[4];
                    ldsm4(t0, bFragNT + jb * 2048 + buoff);
                    b[fb][2 * jb][0] = t0[0]; b[fb][2 * jb][1] = t0[1];
                    b[fb][2 * jb + 1][0] = t0[2]; b[fb][2 * jb + 1][1] = t0[3];
                }
            } else {
                uint32_t kb = bS + (ks * 16 + krow0) * 512;
#pragma unroll
                for (int jb = 0; jb < 4; jb++) {
                    uint32_t t0[4];
                    ldsm4t(t0, kb + (uint32_t)(((nu0 + 2 * jb) ^ l7) << 4));
                    b[fb][2 * jb][0] = t0[0]; b[fb][2 * jb][1] = t0[1];
                    b[fb][2 * jb + 1][0] = t0[2]; b[fb][2 * jb + 1][1] = t0[3];
                }
            }
        };

        load_frag(0, 0);
#pragma unroll
        for (int ks = 0; ks < 4; ks++) {
            const int fb = ks & 1;
            if (ks < 3) load_frag(ks + 1, fb ^ 1);
#pragma unroll
            for (int i = 0; i < 4; i++)
#pragma unroll
                for (int j = 0; j < 8; j++)
                    mma16(acc[i][j], a[fb][i], b[fb][j]);
        }
    }

    // ---- epilogue ----
    const int gr = lane >> 2, tg = lane & 3;
#pragma unroll
    for (int i = 0; i < 4; i++) {
        int r0 = wm * 64 + i * 16 + gr;
#pragma unroll
        for (int j = 0; j < 8; j++) {
            int col = wn * 64 + j * 8 + 2 * tg;
            float b0 = 0.f, b1 = 0.f;
            if (bias) {
                b0 = bias[bx * BN + col];
                b1 = bias[bx * BN + col + 1];
            }
            float v0 = acc[i][j][0] * scale + b0;
            float v1 = acc[i][j][1] * scale + b1;
            float v2 = acc[i][j][2] * scale + b0;
            float v3 = acc[i][j][3] * scale + b1;
            if (relu) {
                v0 = fmaxf(v0, 0.f); v1 = fmaxf(v1, 0.f);
                v2 = fmaxf(v2, 0.f); v3 = fmaxf(v3, 0.f);
            }
            if (OUTB) {
                bf16* C = (bf16*)Cv;
                __nv_bfloat162 p0, p1;
                p0.x = __float2bfloat16(v0); p0.y = __float2bfloat16(v1);
                p1.x = __float2bfloat16(v2); p1.y = __float2bfloat16(v3);
                *(__nv_bfloat162*)(C + cbase + (long long)r0 * ldC + col)       = p0;
                *(__nv_bfloat162*)(C + cbase + (long long)(r0 + 8) * ldC + col) = p1;
            } else {
                if (resid) {
                    float2 q0 = *(const float2*)(resid + cbase + (long long)r0 * ldC + col);
                    float2 q1 = *(const float2*)(resid + cbase + (long long)(r0 + 8) * ldC + col);
                    v0 += q0.x; v1 += q0.y; v2 += q1.x; v3 += q1.y;
                }
                float* C = (float*)Cv;
                *(float2*)(C + cbase + (long long)r0 * ldC + col)       = make_float2(v0, v1);
                *(float2*)(C + cbase + (long long)(r0 + 8) * ldC + col) = make_float2(v2, v3);
            }
        }
    }
}

// ---------------- row softmax: f32 in, bf16 out, with pre-scale ----------------
__global__ __launch_bounds__(256)
void softmax_bf(const float* __restrict__ sc, bf16* __restrict__ pb, float scale)
{
    __shared__ float redm[8], reds[8];
    const long long row = blockIdx.x;
    const float* p = sc + row * (long long)S_;
    bf16* o = pb + row * (long long)S_;
    const int tid = threadIdx.x, lane = tid & 31, wid = tid >> 5;

    float v[8];
    float m = -1e30f;
#pragma unroll
    for (int i = 0; i < 8; i++) {
        v[i] = p[tid + i * 256] * scale;
        m = fmaxf(m, v[i]);
    }
#pragma unroll
    for (int s = 16; s > 0; s >>= 1)
        m = fmaxf(m, __shfl_xor_sync(0xffffffffu, m, s));
    if (lane == 0) redm[wid] = m;
    __syncthreads();
    float mm = redm[0];
#pragma unroll
    for (int i = 1; i < 8; i++) mm = fmaxf(mm, redm[i]);

    float s = 0.f;
#pragma unroll
    for (int i = 0; i < 8; i++) { v[i] = expf(v[i] - mm); s += v[i]; }
#pragma unroll
    for (int t2 = 16; t2 > 0; t2 >>= 1)
        s += __shfl_xor_sync(0xffffffffu, s, t2);
    if (lane == 0) reds[wid] = s;
    __syncthreads();
    float ss = reds[0];
#pragma unroll
    for (int i = 1; i < 8; i++) ss += reds[i];
    float inv = 1.f / ss;
#pragma unroll
    for (int i = 0; i < 8; i++)
        o[tid + i * 256] = __float2bfloat16(v[i] * inv);
}

// ---------------- layernorm: x = LN(s), writes f32 + bf16 (s already has residual) ----
__global__ __launch_bounds__(128)
void ln_kernel(float* __restrict__ x, bf16* __restrict__ xb,
               const float* __restrict__ srow,
               const float* __restrict__ g, const float* __restrict__ b)
{
    __shared__ float red[4], red2[4];
    const long long row = blockIdx.x;
    const int tid = threadIdx.x, lane = tid & 31, wid = tid >> 5;
    float* px = x + row * (long long)D_;
    bf16* pb  = xb + row * (long long)D_;
    const float* ps = srow + row * (long long)D_;

    float v[4];
    float s = 0.f;
#pragma unroll
    for (int i = 0; i < 4; i++) {
        v[i] = ps[tid + i * 128];
        s += v[i];
    }
#pragma unroll
    for (int t2 = 16; t2 > 0; t2 >>= 1)
        s += __shfl_xor_sync(0xffffffffu, s, t2);
    if (lane == 0) red[wid] = s;
    __syncthreads();
    const float mu = (red[0] + red[1] + red[2] + red[3]) * (1.f / D_);

    float sq = 0.f;
#pragma unroll
    for (int i = 0; i < 4; i++) { float d = v[i] - mu; sq += d * d; }
#pragma unroll
    for (int t2 = 16; t2 > 0; t2 >>= 1)
        sq += __shfl_xor_sync(0xffffffffu, sq, t2);
    if (lane == 0) red2[wid] = sq;
    __syncthreads();
    const float rstd = rsqrtf((red2[0] + red2[1] + red2[2] + red2[3]) * (1.f / D_) + 1e-5f);
#pragma unroll
    for (int i = 0; i < 4; i++) {
        int c = tid + i * 128;
        float y = (v[i] - mu) * rstd * g[c] + b[c];
        px[c] = y;
        pb[c] = __float2bfloat16(y);
    }
}

// ---------------- mean-pool over S then dot with clf_w ----------------
__global__ __launch_bounds__(256)
void pool_kernel(const float* __restrict__ x, const float* __restrict__ w,
                 const float* __restrict__ cb, float* __restrict__ out)
{
    __shared__ float red[256];
    const int b = blockIdx.x;
    const int tid = threadIdx.x;
    const float* p = x + (long long)b * S_ * D_;
    float acc = 0.f;
    for (int i = tid; i < S_ * D_; i += 256)
        acc += p[i] * w[i & (D_ - 1)];
    red[tid] = acc; __syncthreads();
    for (int o = 128; o > 0; o >>= 1) {
        if (tid < o) red[tid] += red[tid + o];
        __syncthreads();
    }
    if (tid == 0) out[b] = red[0] * (1.f / (float)S_) + cb[0];
}

// ---------------- host orchestration ----------------
extern "C" void kernel_launch(void* const* d_in, const int* in_sizes, int n_in,
                              void* d_out, int out_size)
{
    (void)in_sizes; (void)n_in; (void)out_size;
    const int*   tokens = (const int*)  d_in[0];
    const float* emb    = (const float*)d_in[1];
    const float* Wq     = (const float*)d_in[2];
    const float* bq     = (const float*)d_in[3];
    const float* Wk     = (const float*)d_in[4];
    const float* bk     = (const float*)d_in[5];
    const float* Wv     = (const float*)d_in[6];
    const float* bv     = (const float*)d_in[7];
    const float* Wo     = (const float*)d_in[8];
    const float* bo     = (const float*)d_in[9];
    const float* W1     = (const float*)d_in[10];
    const float* b1     = (const float*)d_in[11];
    const float* W2     = (const float*)d_in[12];
    const float* b2     = (const float*)d_in[13];
    const float* ln1g   = (const float*)d_in[14];
    const float* ln1b   = (const float*)d_in[15];
    const float* ln2g   = (const float*)d_in[16];
    const float* ln2b   = (const float*)d_in[17];
    const float* clfw   = (const float*)d_in[18];
    const float* clfb   = (const float*)d_in[19];
    float* out = (float*)d_out;

    float *x, *r, *sc, *bqkv;
    bf16 *xb, *qkv, *tb, *hb, *pb;
    bf16 *wqkv, *wob, *w1b, *w2b;
    cudaGetSymbolAddress((void**)&x,    g_x);
    cudaGetSymbolAddress((void**)&r,    g_r);
    cudaGetSymbolAddress((void**)&sc,   g_sc);
    cudaGetSymbolAddress((void**)&xb,   g_xb);
    cudaGetSymbolAddress((void**)&qkv,  g_qkv);
    cudaGetSymbolAddress((void**)&tb,   g_tb);
    cudaGetSymbolAddress((void**)&hb,   g_hb);
    cudaGetSymbolAddress((void**)&pb,   g_pb);
    cudaGetSymbolAddress((void**)&wqkv, g_wqkv);
    cudaGetSymbolAddress((void**)&bqkv, g_bqkv);
    cudaGetSymbolAddress((void**)&wob,  g_wob);
    cudaGetSymbolAddress((void**)&w1b,  g_w1b);
    cudaGetSymbolAddress((void**)&w2b,  g_w2b);

    cudaFuncSetAttribute(gemm_bf<0,1>, cudaFuncAttributeMaxDynamicSharedMemorySize, SMEM_BYTES);
    cudaFuncSetAttribute(gemm_bf<0,0>, cudaFuncAttributeMaxDynamicSharedMemorySize, SMEM_BYTES);
    cudaFuncSetAttribute(gemm_bf<1,0>, cudaFuncAttributeMaxDynamicSharedMemorySize, SMEM_BYTES);

    // weight conversion / concatenation (idempotent per launch)
    cvt_qkv_w<<<(L_ * D_ * D_) / 256, 256>>>(Wq, Wk, Wv, wqkv);
    cvt_qkv_b<<<(L_ * D_) / 256, 256>>>(bq, bk, bv, bqkv);
    cvt_bf<<<(L_ * D_ * D_) / 256, 256>>>(Wo, wob);
    cvt_bf<<<(L_ * D_ * F_) / 256, 256>>>(W1, w1b);
    cvt_bf<<<(L_ * D_ * F_) / 256, 256>>>(W2, w2b);

    embed_kernel<<<(BS_ * D_) / 256, 256>>>(tokens, emb, x, xb);

    const dim3 gQKV(D3_ / BN, BS_ / BM, 1);      // 6 x 128 = 768 CTAs
    const dim3 gProj(D_ / BN, BS_ / BM, 1);      // 2 x 128
    const dim3 gScores(S_ / BN, S_ / BM, B_);    // 8 x 16 x 8
    const dim3 gAV(D_ / BN, S_ / BM, B_);        // 2 x 16 x 8
    const dim3 gF1(F_ / BN, BS_ / BM, 1);        // 8 x 128
    const float kscale = 0.044194173824159216f;  // 1/sqrt(512)

    for (int l = 0; l < L_; l++) {
        const bf16* Wqkv_l = wqkv + (size_t)l * D_ * D3_;
        const float* bqkv_l = bqkv + (size_t)l * D3_;
        const bf16* Wo_l = wob + (size_t)l * D_ * D_;
        const bf16* W1_l = w1b + (size_t)l * D_ * F_;
        const bf16* W2_l = w2b + (size_t)l * F_ * D_;
        const float* bo_l = bo + (size_t)l * D_;
        const float* b1_l = b1 + (size_t)l * F_;
        const float* b2_l = b2 + (size_t)l * D_;

        // fused QKV: qkv[BS,1536] = xb @ Wqkv + bqkv
        gemm_bf<0, 1><<<gQKV, 256, SMEM_BYTES>>>(xb, Wqkv_l, bqkv_l, nullptr, qkv,
                                                 D_, D_, D3_, D3_, 0, 0, 0, 1.f, 0);

        // scores[b] = Q_b @ K_b^T (f32; scale applied in softmax)
        gemm_bf<1, 0><<<gScores, 256, SMEM_BYTES>>>(qkv, qkv + D_, nullptr, nullptr, sc,
                                                    D_, D3_, D3_, S_,
                                                    (long long)S_ * D3_, (long long)S_ * D3_,
                                                    (long long)S_ * S_, 1.f, 0);
        softmax_bf<<<B_ * S_, 256>>>(sc, pb, kscale);

        // t[b] = P_b @ V_b (bf16 out)
        gemm_bf<0, 1><<<gAV, 256, SMEM_BYTES>>>(pb, qkv + 2 * D_, nullptr, nullptr, tb,
                                                S_, S_, D3_, D_,
                                                (long long)S_ * S_, (long long)S_ * D3_,
                                                (long long)S_ * D_, 1.f, 0);

        // r = x + (t @ Wo + bo)  (residual fused into epilogue)
        gemm_bf<0, 0><<<gProj, 256, SMEM_BYTES>>>(tb, Wo_l, bo_l, x, r,
                                                  D_, D_, D_, D_, 0, 0, 0, 1.f, 0);
        ln_kernel<<<BS_, 128>>>(x, xb, r, ln1g + (size_t)l * D_, ln1b + (size_t)l * D_);

        // FFN
        gemm_bf<0, 1><<<gF1, 256, SMEM_BYTES>>>(xb, W1_l, b1_l, nullptr, hb,
                                                D_, D_, F_, F_, 0, 0, 0, 1.f, 1);
        // r = x + (h @ W2 + b2)  (residual fused into epilogue)
        gemm_bf<0, 0><<<gProj, 256, SMEM_BYTES>>>(hb, W2_l, b2_l, x, r,
                                                  F_, F_, D_, D_, 0, 0, 0, 1.f, 0);
        ln_kernel<<<BS_, 128>>>(x, xb, r, ln2g + (size_t)l * D_, ln2b + (size_t)l * D_);
    }

    pool_kernel<<<B_, 256>>>(x, clfw, clfb, out);
}